// round 12
// baseline (speedup 1.0000x reference)
#include <cuda_runtime.h>
#include <cuda_bf16.h>
#include <math.h>
#include <cstdint>

#define NN 100000
#define NR 8
#define NE 400000
#define DD 128
#define NL 3
#define NP1 (NN + 1)

#define SCAN_B 512
#define NBLK ((NN + SCAN_B - 1) / SCAN_B)   // 196

// ---------------- device scratch (static, no allocations) ----------------
__device__ float    g_bufA[NN * DD];
__device__ float    g_bufB[NN * DD];
__device__ float    g_el[NR * NN];
__device__ float    g_er[NR * NN];
__device__ float    g_vl[NR * DD];
__device__ float    g_vr[NR * DD];
__device__ uint32_t g_qwh[NR * DD * DD / 4];       // W hi int8, packed
__device__ uint32_t g_qwl[NR * DD * DD / 4];       // W lo int8, packed
__device__ float    g_sB[NR * DD];                 // W row scales
__device__ uint32_t g_qyh[(size_t)NR * NN * 32];   // y hi int8, packed
__device__ uint32_t g_qyl[(size_t)NR * NN * 32];   // y lo int8, packed
__device__ float    g_sA[(size_t)NR * NN];         // y row scales
__device__ int      g_cnt[NR * NN];
__device__ int      g_fill[NR * NN];
__device__ int      g_rowptr[NR * NP1];
__device__ int      g_bsum[NR * NBLK];
__device__ int      g_csrc[(size_t)NR * NE];

// ====================== CSR build (R5-proven) ==============================
__global__ void hist_kernel(const int* __restrict__ edst) {
    int i = blockIdx.x * 256 + threadIdx.x;
    int r = blockIdx.y;
    if (i >= NE) return;
    int d = edst[(size_t)r * NE + i];
    atomicAdd(&g_cnt[r * NN + d], 1);
}

__global__ void scan1_kernel() {
    __shared__ int sh[SCAN_B];
    int r = blockIdx.y;
    int tid = threadIdx.x;
    int i = blockIdx.x * SCAN_B + tid;
    int v = (i < NN) ? g_cnt[r * NN + i] : 0;
    sh[tid] = v;
    __syncthreads();
    for (int off = 1; off < SCAN_B; off <<= 1) {
        int t = (tid >= off) ? sh[tid - off] : 0;
        __syncthreads();
        sh[tid] += t;
        __syncthreads();
    }
    int incl = sh[tid];
    if (i < NN) g_rowptr[r * NP1 + i] = incl - v;
    if (tid == SCAN_B - 1) g_bsum[r * NBLK + blockIdx.x] = incl;
}

__global__ void scan2_kernel() {
    int r = blockIdx.x;
    if (threadIdx.x != 0) return;
    int run = 0;
    for (int b = 0; b < NBLK; b++) {
        int t = g_bsum[r * NBLK + b];
        g_bsum[r * NBLK + b] = run;
        run += t;
    }
}

__global__ void scan3_kernel() {
    int r = blockIdx.y;
    int i = blockIdx.x * SCAN_B + threadIdx.x;
    if (i < NN) g_rowptr[r * NP1 + i] += g_bsum[r * NBLK + blockIdx.x];
    if (blockIdx.x == 0 && threadIdx.x == 0) g_rowptr[r * NP1 + NN] = NE;
}

__global__ void fill_kernel(const int* __restrict__ esrc,
                            const int* __restrict__ edst) {
    int i = blockIdx.x * 256 + threadIdx.x;
    int r = blockIdx.y;
    if (i >= NE) return;
    int d = edst[(size_t)r * NE + i];
    int s = esrc[(size_t)r * NE + i];
    int pos = g_rowptr[r * NP1 + d] + atomicAdd(&g_fill[r * NN + d], 1);
    g_csrc[(size_t)r * NE + pos] = s;
}

// -------- quantize helper: v -> (hi, lo) with v ~= s*(256*hi+lo)/32512 -----
__device__ __forceinline__ void quant16(float v, float inv, int& h, int& l) {
    float q = v * inv;                       // |q| <= 127
    h = __float2int_rn(q);
    l = __float2int_rn((q - (float)h) * 256.f);
    l = max(-127, min(127, l));
}

// ---------------- fused: W int8 quant + vl/vr vectors ----------------------
// blocks 0..127: quantize W rows (8 warps = 8 rows each)
// blocks 128..143: vecs (128 active threads)
__global__ void prep_wv_kernel(const float* __restrict__ Wsrc,
                               const float* __restrict__ Wdst,
                               const float* __restrict__ al,
                               const float* __restrict__ ar) {
    const unsigned F = 0xffffffffu;
    int b = blockIdx.x;
    if (b < 128) {
        int row = b * 8 + (threadIdx.x >> 5);    // 0..1023 (= r*128 + n)
        int lane = threadIdx.x & 31;
        float4 v = ((const float4*)(Wsrc + (size_t)row * DD))[lane];
        float m4 = fmaxf(fmaxf(fabsf(v.x), fabsf(v.y)),
                         fmaxf(fabsf(v.z), fabsf(v.w)));
#pragma unroll
        for (int off = 16; off; off >>= 1)
            m4 = fmaxf(m4, __shfl_xor_sync(F, m4, off));
        float inv = m4 > 0.f ? 127.f / m4 : 0.f;
        int h0, h1, h2, h3, l0, l1, l2, l3;
        quant16(v.x, inv, h0, l0); quant16(v.y, inv, h1, l1);
        quant16(v.z, inv, h2, l2); quant16(v.w, inv, h3, l3);
        uint32_t ph = (h0 & 255) | ((h1 & 255) << 8) | ((h2 & 255) << 16)
                      | ((h3 & 255) << 24);
        uint32_t pl = (l0 & 255) | ((l1 & 255) << 8) | ((l2 & 255) << 16)
                      | ((l3 & 255) << 24);
        g_qwh[row * 32 + lane] = ph;
        g_qwl[row * 32 + lane] = pl;
        if (lane == 0) g_sB[row] = m4;
    } else if (threadIdx.x < 128) {
        int bb = b - 128;            // 0..15
        int r = bb >> 1;
        int k = threadIdx.x;
        const float* W = (bb & 1) ? (Wdst + r * DD * DD) : (Wsrc + r * DD * DD);
        const float* a = (bb & 1) ? (ar + r * DD) : (al + r * DD);
        float s = 0.f;
#pragma unroll 8
        for (int j = 0; j < DD; j++) s += a[j] * W[j * DD + k];
        float* o = (bb & 1) ? g_vr : g_vl;
        o[r * DD + k] = s;
    }
}

// ---------------- el[r][n] = x[n]·vl[r], er[r][n] = x[n]·vr[r] ------------
__global__ void scores_kernel(const float* __restrict__ x) {
    __shared__ float xs[32][133];
    __shared__ float vv[16][DD];
    int tid = threadIdx.x;       // 128 threads
    int n0 = blockIdx.x * 32;

    for (int i = tid; i < 16 * DD; i += 128) {
        int v = i >> 7, k = i & 127;
        vv[v][k] = (v < 8) ? g_vl[v * DD + k] : g_vr[(v - 8) * DD + k];
    }
    for (int i = tid; i < 32 * DD; i += 128) {
        int r = i >> 7, k = i & 127;
        xs[r][k] = x[(size_t)(n0 + r) * DD + k];
    }
    __syncthreads();

    int node = tid & 31;
    int v0 = (tid >> 5) * 4;
    float a0 = 0.f, a1 = 0.f, a2 = 0.f, a3 = 0.f;
#pragma unroll 8
    for (int k = 0; k < DD; k++) {
        float xv = xs[node][k];
        a0 += xv * vv[v0 + 0][k];
        a1 += xv * vv[v0 + 1][k];
        a2 += xv * vv[v0 + 2][k];
        a3 += xv * vv[v0 + 3][k];
    }
    int n = n0 + node;
    float acc[4] = {a0, a1, a2, a3};
#pragma unroll
    for (int j = 0; j < 4; j++) {
        int v = v0 + j;
        if (v < 8) g_el[v * NN + n] = acc[j];
        else       g_er[(v - 8) * NN + n] = acc[j];
    }
}

// =================== aggregation: y[r][d] = softmax-weighted mean ==========
// One warp per (dst, relation). R10-proven core; epilogue quantizes the y row
// to 16-bit fixed point (int8 hi/lo + per-row scale).
__global__ void __launch_bounds__(256)
agg_kernel(const float* __restrict__ x) {
    const unsigned F = 0xffffffffu;
    int lane = threadIdx.x & 31;
    int d = blockIdx.x * 8 + (threadIdx.x >> 5);
    int r = blockIdx.y;
    if (d >= NN) return;

    const int* rp = g_rowptr + r * NP1;
    const int* cs = g_csrc + (size_t)r * NE;
    const float* elr = g_el + (size_t)r * NN;
    const float4* x4 = (const float4*)x;

    int st = rp[d], en = rp[d + 1];
    float ax = 0.f, ay = 0.f, az = 0.f, aw = 0.f;
    float den = 0.f;
    if (st < en) {
        float er_d = g_er[(size_t)r * NN + d];
        for (int base = st; base < en; base += 32) {
            int c = en - base;
            if (c > 32) c = 32;
            float w = 0.f;
            int s = 0;
            if (lane < c) {
                s = cs[base + lane];
                float v = elr[s] + er_d;
                v = v > 0.f ? v : 0.2f * v;
                w = expf(v);
            }
            float ws = w;
#pragma unroll
            for (int off = 16; off; off >>= 1)
                ws += __shfl_xor_sync(F, ws, off);
            den += ws;
            for (int j = 0; j < c; j++) {
                float wj = __shfl_sync(F, w, j);
                int sj = __shfl_sync(F, s, j);
                float4 xv = x4[(size_t)sj * 32 + lane];
                ax += wj * xv.x;
                ay += wj * xv.y;
                az += wj * xv.z;
                aw += wj * xv.w;
            }
        }
        float inv = 1.f / den;
        ax *= inv; ay *= inv; az *= inv; aw *= inv;
    }
    // ---- quantize row: per-row scale + int8 hi/lo ----
    float m4 = fmaxf(fmaxf(fabsf(ax), fabsf(ay)), fmaxf(fabsf(az), fabsf(aw)));
#pragma unroll
    for (int off = 16; off; off >>= 1)
        m4 = fmaxf(m4, __shfl_xor_sync(F, m4, off));
    float qinv = m4 > 0.f ? 127.f / m4 : 0.f;
    int h0, h1, h2, h3, l0, l1, l2, l3;
    quant16(ax, qinv, h0, l0); quant16(ay, qinv, h1, l1);
    quant16(az, qinv, h2, l2); quant16(aw, qinv, h3, l3);
    uint32_t ph = (h0 & 255) | ((h1 & 255) << 8) | ((h2 & 255) << 16)
                  | ((h3 & 255) << 24);
    uint32_t pl = (l0 & 255) | ((l1 & 255) << 8) | ((l2 & 255) << 16)
                  | ((l3 & 255) << 24);
    size_t o32 = ((size_t)r * NN + d) * 32 + lane;
    __stcs(&g_qyh[o32], ph);
    __stcs(&g_qyl[o32], pl);
    if (lane == 0) g_sA[(size_t)r * NN + d] = m4;
}

// =================== int8 MMA GEMM over quantized y ========================
// out[m] = [relu]( sum_r y[r][m] @ W[r]^T + bias )
// 16-bit fixed-point split: v = s*(256*hi+lo)/32512.  Per k32 chunk:
//   hh += Ahi*Bhi ; xx += Ahi*Blo + Alo*Bhi   (drop lo*lo ~2^-16)
//   contrib = sA*sB*(65536*hh + 256*xx)/32512^2
#define PADB 144
#define MTILE 64

#define SQA_HI 0
#define SQA_LO (MTILE * PADB)                 // 9216
#define SQB_HI (2 * MTILE * PADB)             // 18432
#define SQB_LO (SQB_HI + 128 * PADB)          // 36864
#define SSB    (SQB_LO + 128 * PADB)          // 55296
#define SM_TOTAL (SSB + 512)                  // 55808

__device__ __forceinline__ void mma_s8(int* c, const uint32_t* a,
                                       const uint32_t* b) {
    asm volatile(
        "mma.sync.aligned.m16n8k32.row.col.s32.s8.s8.s32 "
        "{%0,%1,%2,%3}, {%4,%5,%6,%7}, {%8,%9}, {%0,%1,%2,%3};"
        : "+r"(c[0]), "+r"(c[1]), "+r"(c[2]), "+r"(c[3])
        : "r"(a[0]), "r"(a[1]), "r"(a[2]), "r"(a[3]), "r"(b[0]), "r"(b[1]));
}

__global__ void __launch_bounds__(256)
gemm_agg_kernel(float* __restrict__ out, const float* __restrict__ bias,
                int relu) {
    extern __shared__ char smem[];
    char* Ash = smem + SQA_HI;
    char* Asl = smem + SQA_LO;
    char* Bsh = smem + SQB_HI;
    char* Bsl = smem + SQB_LO;
    float* sBs = (float*)(smem + SSB);

    int tid = threadIdx.x;
    int wid = tid >> 5;
    int lane = tid & 31;
    int m0 = blockIdx.x * MTILE;

    int wm = (wid >> 2) * 32;    // 2 warps in m
    int wn = (wid & 3) * 32;     // 4 warps in n
    int g4 = lane >> 2;
    int tig = lane & 3;

    const float c1 = 65536.f / (32512.f * 32512.f);
    const float c2 = 256.f / (32512.f * 32512.f);

    float accF[2][4][4];
#pragma unroll
    for (int mt = 0; mt < 2; mt++)
#pragma unroll
        for (int nt = 0; nt < 4; nt++)
#pragma unroll
            for (int j = 0; j < 4; j++) accF[mt][nt][j] = 0.f;

    const uint4* qy4h = (const uint4*)g_qyh;
    const uint4* qy4l = (const uint4*)g_qyl;

    for (int r = 0; r < NR; r++) {
        __syncthreads();   // prior MMA done reading smem

        const uint4* wh4 = (const uint4*)g_qwh + r * 1024;
        const uint4* wl4 = (const uint4*)g_qwl + r * 1024;
        // B tile: 128 rows x 128B = 1024 uint4 chunks
#pragma unroll
        for (int it = 0; it < 4; it++) {
            int idx = tid + it * 256;
            int row = idx >> 3, c16 = idx & 7;
            *(uint4*)(Bsh + row * PADB + c16 * 16) = wh4[idx];
            *(uint4*)(Bsl + row * PADB + c16 * 16) = wl4[idx];
        }
        // A tile: 64 rows x 128B = 512 chunks
#pragma unroll
        for (int it = 0; it < 2; it++) {
            int idx = tid + it * 256;
            int row = idx >> 3, c16 = idx & 7;
            uint4 vh = make_uint4(0, 0, 0, 0), vl = make_uint4(0, 0, 0, 0);
            if (m0 + row < NN) {
                size_t gi = ((size_t)r * NN + m0 + row) * 8 + c16;
                vh = __ldcs(&qy4h[gi]);
                vl = __ldcs(&qy4l[gi]);
            }
            *(uint4*)(Ash + row * PADB + c16 * 16) = vh;
            *(uint4*)(Asl + row * PADB + c16 * 16) = vl;
        }
        if (tid < 128) sBs[tid] = g_sB[r * DD + tid];
        __syncthreads();

        // ---- int8 MMA, nt processed in 2 groups to bound registers ----
#pragma unroll
        for (int ntg = 0; ntg < 2; ntg++) {
            int hh[2][2][4] = {}, xx[2][2][4] = {};
#pragma unroll
            for (int kc = 0; kc < 4; kc++) {
                uint32_t ah[2][4], al_[2][4];
#pragma unroll
                for (int mt = 0; mt < 2; mt++) {
                    int arow = wm + mt * 16 + g4;
                    int ab = arow * PADB + kc * 32 + tig * 4;
                    ah[mt][0] = *(const uint32_t*)(Ash + ab);
                    ah[mt][1] = *(const uint32_t*)(Ash + ab + 8 * PADB);
                    ah[mt][2] = *(const uint32_t*)(Ash + ab + 16);
                    ah[mt][3] = *(const uint32_t*)(Ash + ab + 8 * PADB + 16);
                    al_[mt][0] = *(const uint32_t*)(Asl + ab);
                    al_[mt][1] = *(const uint32_t*)(Asl + ab + 8 * PADB);
                    al_[mt][2] = *(const uint32_t*)(Asl + ab + 16);
                    al_[mt][3] = *(const uint32_t*)(Asl + ab + 8 * PADB + 16);
                }
                uint32_t bh[2][2], bl_[2][2];
#pragma unroll
                for (int ntl = 0; ntl < 2; ntl++) {
                    int n = wn + (ntg * 2 + ntl) * 8 + g4;
                    int bb = n * PADB + kc * 32 + tig * 4;
                    bh[ntl][0] = *(const uint32_t*)(Bsh + bb);
                    bh[ntl][1] = *(const uint32_t*)(Bsh + bb + 16);
                    bl_[ntl][0] = *(const uint32_t*)(Bsl + bb);
                    bl_[ntl][1] = *(const uint32_t*)(Bsl + bb + 16);
                }
#pragma unroll
                for (int mt = 0; mt < 2; mt++)
#pragma unroll
                    for (int ntl = 0; ntl < 2; ntl++) {
                        mma_s8(hh[mt][ntl], ah[mt], bh[ntl]);
                        mma_s8(xx[mt][ntl], ah[mt], bl_[ntl]);
                        mma_s8(xx[mt][ntl], al_[mt], bh[ntl]);
                    }
            }
            // ---- dequant into float accumulators ----
#pragma unroll
            for (int mt = 0; mt < 2; mt++) {
                int row0 = m0 + wm + mt * 16 + g4;
                int row1 = row0 + 8;
                float sA0 = row0 < NN ? g_sA[(size_t)r * NN + row0] : 0.f;
                float sA1 = row1 < NN ? g_sA[(size_t)r * NN + row1] : 0.f;
#pragma unroll
                for (int ntl = 0; ntl < 2; ntl++) {
                    int nt = ntg * 2 + ntl;
                    int col = wn + nt * 8 + tig * 2;
                    float sB0 = sBs[col], sB1 = sBs[col + 1];
                    float t0 = c1 * (float)hh[mt][ntl][0] + c2 * (float)xx[mt][ntl][0];
                    float t1 = c1 * (float)hh[mt][ntl][1] + c2 * (float)xx[mt][ntl][1];
                    float t2 = c1 * (float)hh[mt][ntl][2] + c2 * (float)xx[mt][ntl][2];
                    float t3 = c1 * (float)hh[mt][ntl][3] + c2 * (float)xx[mt][ntl][3];
                    accF[mt][nt][0] += sA0 * sB0 * t0;
                    accF[mt][nt][1] += sA0 * sB1 * t1;
                    accF[mt][nt][2] += sA1 * sB0 * t2;
                    accF[mt][nt][3] += sA1 * sB1 * t3;
                }
            }
        }
    }

    // ---- epilogue: bias (+relu), streaming store ----
#pragma unroll
    for (int mt = 0; mt < 2; mt++) {
        int row0 = m0 + wm + mt * 16 + g4;
        int row1 = row0 + 8;
#pragma unroll
        for (int nt = 0; nt < 4; nt++) {
            int col = wn + nt * 8 + tig * 2;
            float b0 = bias[col], b1 = bias[col + 1];
            float v0 = accF[mt][nt][0] + b0, v1 = accF[mt][nt][1] + b1;
            float v2 = accF[mt][nt][2] + b0, v3 = accF[mt][nt][3] + b1;
            if (relu) {
                v0 = fmaxf(v0, 0.f); v1 = fmaxf(v1, 0.f);
                v2 = fmaxf(v2, 0.f); v3 = fmaxf(v3, 0.f);
            }
            if (row0 < NN)
                __stcs((float2*)(out + (size_t)row0 * DD + col),
                       make_float2(v0, v1));
            if (row1 < NN)
                __stcs((float2*)(out + (size_t)row1 * DD + col),
                       make_float2(v2, v3));
        }
    }
}

// ===========================================================================
extern "C" void kernel_launch(void* const* d_in, const int* in_sizes, int n_in,
                              void* d_out, int out_size) {
    const float* h    = (const float*)d_in[0];
    const int*   esrc = (const int*)d_in[1];
    const int*   edst = (const int*)d_in[2];
    const float* fsw  = (const float*)d_in[3];
    const float* fdw  = (const float*)d_in[4];
    const float* al   = (const float*)d_in[5];
    const float* ar   = (const float*)d_in[6];
    const float* hb   = (const float*)d_in[7];
    float* out_final  = (float*)d_out;

    float *bufA, *bufB;
    int *cnt, *fill;
    cudaGetSymbolAddress((void**)&bufA, g_bufA);
    cudaGetSymbolAddress((void**)&bufB, g_bufB);
    cudaGetSymbolAddress((void**)&cnt,  g_cnt);
    cudaGetSymbolAddress((void**)&fill, g_fill);

    cudaFuncSetAttribute(gemm_agg_kernel,
                         cudaFuncAttributeMaxDynamicSharedMemorySize, SM_TOTAL);

    // ---- CSR build (R5-proven parallel scan) ----
    cudaMemsetAsync(cnt, 0, NR * NN * sizeof(int));
    cudaMemsetAsync(fill, 0, NR * NN * sizeof(int));
    hist_kernel<<<dim3((NE + 255) / 256, NR), 256>>>(edst);
    scan1_kernel<<<dim3(NBLK, NR), SCAN_B>>>();
    scan2_kernel<<<NR, 32>>>();
    scan3_kernel<<<dim3(NBLK, NR), SCAN_B>>>();
    fill_kernel<<<dim3((NE + 255) / 256, NR), 256>>>(esrc, edst);

    const int MT = (NN + MTILE - 1) / MTILE;   // 1563

    const float* x = h;
    for (int l = 0; l < NL; l++) {
        float* out = (l == 0) ? bufB : (l == 1) ? bufA : out_final;

        prep_wv_kernel<<<144, 256>>>(fsw + (size_t)l * NR * DD * DD,
                                     fdw + (size_t)l * NR * DD * DD,
                                     al + l * NR * DD, ar + l * NR * DD);
        scores_kernel<<<NN / 32, 128>>>(x);

        agg_kernel<<<dim3((NN + 7) / 8, NR), 256>>>(x);
        gemm_agg_kernel<<<MT, 256, SM_TOTAL>>>(out, hb + l * DD,
                                               l < NL - 1 ? 1 : 0);
        x = out;
    }
}

// round 13
// speedup vs baseline: 1.5922x; 1.5922x over previous
#include <cuda_runtime.h>
#include <cuda_bf16.h>
#include <math.h>
#include <cstdint>

#define NN 100000
#define NR 8
#define NE 400000
#define DD 128
#define NL 3

#define SNB 1563                 // scan blocks: ceil(800000/512)
#define FILLB 1563               // fill blocks per relation: ceil(NE/256)

// ---------------- device scratch (static, no allocations) ----------------
__device__ float         g_bufA[NN * DD];
__device__ float         g_bufB[NN * DD];
__device__ float         g_el[NR * NN];
__device__ float         g_er[NR * NN];
__device__ float         g_vl[NL * NR * DD];
__device__ float         g_vr[NL * NR * DD];
__device__ __nv_bfloat16 g_whi[(size_t)NL * NR * DD * DD];
__device__ __nv_bfloat16 g_wlo[(size_t)NL * NR * DD * DD];
__device__ __nv_bfloat16 g_yhi[(size_t)NR * NN * DD];
__device__ __nv_bfloat16 g_ylo[(size_t)NR * NN * DD];
__device__ int           g_cnt[NR * NN];       // zero at start; reset by scan
__device__ int           g_fill[NR * NN];      // reset by scan
__device__ int           g_rowptrF[NR * NN + 1];
__device__ int           g_csrc[(size_t)NR * NE];
__device__ int           g_state[SNB];         // lookback: (value<<2)|flag
__device__ int           g_ticket;

// =================== kernel 1: hist + scan-state reset =====================
__global__ void hist_kernel(const int* __restrict__ edst) {
    int b = blockIdx.x;
    int tid = threadIdx.x;
    if (b < NR * FILLB) {
        int r = b / FILLB;
        int i = (b % FILLB) * 256 + tid;
        if (i < NE) {
            int d = edst[(size_t)r * NE + i];
            atomicAdd(&g_cnt[r * NN + d], 1);
        }
    } else {
        int i = (b - NR * FILLB) * 256 + tid;
        if (i < SNB) g_state[i] = 0;
        if (i == 0) g_ticket = 0;
    }
}

// =================== kernel 2: lookback scan + W prep + vecs ===============
// blocks [0,SNB): decoupled-lookback exclusive scan of flattened g_cnt ->
//   g_rowptrF (global prefix; per-relation offset is implicit since each
//   relation sums to NE). Also resets g_cnt/g_fill for the next replay.
// blocks [SNB, SNB+768): bf16 hi/lo split of ALL layers' Wsrc.
// blocks [SNB+768, SNB+816): vl/vr vectors for all layers.
__global__ void __launch_bounds__(512)
scan_prep_kernel(const float* __restrict__ fsw,
                 const float* __restrict__ fdw,
                 const float* __restrict__ al,
                 const float* __restrict__ ar) {
    int b = blockIdx.x;
    int tid = threadIdx.x;
    if (b < SNB) {
        __shared__ int sh[512];
        __shared__ int sbc[2];    // [0]=vid, [1]=running prefix
        if (tid == 0) sbc[0] = atomicAdd(&g_ticket, 1);
        __syncthreads();
        int vid = sbc[0];
        int e = vid * 512 + tid;
        int v = 0;
        if (e < NR * NN) {
            v = g_cnt[e];
            g_cnt[e] = 0;
            g_fill[e] = 0;
        }
        sh[tid] = v;
        __syncthreads();
#pragma unroll
        for (int off = 1; off < 512; off <<= 1) {
            int t = (tid >= off) ? sh[tid - off] : 0;
            __syncthreads();
            sh[tid] += t;
            __syncthreads();
        }
        int incl = sh[tid];
        int btot = sh[511];
        if (tid == 0) {
            atomicExch(&g_state[vid], (btot << 2) | 1);   // publish aggregate
            int run = 0;
            int p = vid - 1;
            while (p >= 0) {
                int w = atomicAdd(&g_state[p], 0);
                int f = w & 3;
                if (f == 0) continue;         // spin: predecessor not ready
                run += (w >> 2);
                if (f == 2) break;            // inclusive prefix found
                p--;
            }
            atomicExch(&g_state[vid], ((run + btot) << 2) | 2);
            sbc[1] = run;
            if (vid == SNB - 1) {
                g_rowptrF[NR * NN] = run + btot;
                g_ticket = 0;                 // reset for next replay
            }
        }
        __syncthreads();
        int run = sbc[1];
        if (e < NR * NN) g_rowptrF[e] = run + incl - v;   // exclusive
    } else if (b < SNB + 768) {
        // W hi/lo split, all layers: NL*NR*DD*DD = 393216 = 768*512
        int i = (b - SNB) * 512 + tid;
        float v = fsw[i];
        __nv_bfloat16 hi = __float2bfloat16_rn(v);
        g_whi[i] = hi;
        g_wlo[i] = __float2bfloat16_rn(v - __bfloat162float(hi));
    } else if (tid < 128) {
        int bb = b - SNB - 768;       // 0..47
        int l = bb >> 4;
        int sub = bb & 15;
        int r = sub >> 1;
        size_t wo = ((size_t)l * NR + r) * DD * DD;
        const float* W = (sub & 1) ? (fdw + wo) : (fsw + wo);
        const float* a = ((sub & 1) ? ar : al) + (l * NR + r) * DD;
        int k = tid;
        float s = 0.f;
#pragma unroll 8
        for (int j = 0; j < DD; j++) s += a[j] * W[j * DD + k];
        float* o = (sub & 1) ? g_vr : g_vl;
        o[(l * NR + r) * DD + k] = s;
    }
}

// -------- scores block body (256 threads) ----------------------------------
__device__ __forceinline__ void scores_block(const float* __restrict__ x,
                                             const float* __restrict__ vl,
                                             const float* __restrict__ vr,
                                             int n0) {
    __shared__ float xs[32][133];
    __shared__ float vv[16][DD];
    int tid = threadIdx.x;    // 256
    for (int i = tid; i < 16 * DD; i += 256) {
        int v = i >> 7, k = i & 127;
        vv[v][k] = (v < 8) ? vl[v * DD + k] : vr[(v - 8) * DD + k];
    }
    for (int i = tid; i < 32 * DD; i += 256) {
        int r = i >> 7, k = i & 127;
        xs[r][k] = x[(size_t)(n0 + r) * DD + k];
    }
    __syncthreads();

    int node = tid & 31;
    int v0 = (tid >> 5) * 2;      // 8 warps x 2 vectors
    float a0 = 0.f, a1 = 0.f;
#pragma unroll 8
    for (int k = 0; k < DD; k++) {
        float xv = xs[node][k];
        a0 += xv * vv[v0][k];
        a1 += xv * vv[v0 + 1][k];
    }
    int n = n0 + node;
    if (v0 < 8) g_el[v0 * NN + n] = a0;
    else        g_er[(v0 - 8) * NN + n] = a0;
    int v1 = v0 + 1;
    if (v1 < 8) g_el[v1 * NN + n] = a1;
    else        g_er[(v1 - 8) * NN + n] = a1;
}

// =================== kernel 3: CSR fill + layer-0 scores ===================
__global__ void __launch_bounds__(256)
fill_scores_kernel(const int* __restrict__ esrc,
                   const int* __restrict__ edst,
                   const float* __restrict__ x,
                   const float* __restrict__ vl0,
                   const float* __restrict__ vr0) {
    int b = blockIdx.x;
    if (b < NR * FILLB) {
        int r = b / FILLB;
        int i = (b % FILLB) * 256 + threadIdx.x;
        if (i < NE) {
            int d = edst[(size_t)r * NE + i];
            int s = esrc[(size_t)r * NE + i];
            int pos = g_rowptrF[r * NN + d] + atomicAdd(&g_fill[r * NN + d], 1);
            g_csrc[pos] = s;
        }
    } else {
        scores_block(x, vl0, vr0, (b - NR * FILLB) * 32);
    }
}

// =================== standalone scores (layers 1,2) ========================
__global__ void __launch_bounds__(256)
scores_kernel(const float* __restrict__ x,
              const float* __restrict__ vl,
              const float* __restrict__ vr) {
    scores_block(x, vl, vr, blockIdx.x * 32);
}

// =================== aggregation (R11-proven core, flat CSR) ===============
__device__ __forceinline__ uint32_t pack_bf2(__nv_bfloat16 a, __nv_bfloat16 b) {
    return (uint32_t)__bfloat16_as_ushort(a) |
           ((uint32_t)__bfloat16_as_ushort(b) << 16);
}

__global__ void __launch_bounds__(256)
agg_kernel(const float* __restrict__ x) {
    const unsigned F = 0xffffffffu;
    int lane = threadIdx.x & 31;
    int d = blockIdx.x * 8 + (threadIdx.x >> 5);
    int r = blockIdx.y;
    if (d >= NN) return;

    const int* rp = g_rowptrF + (size_t)r * NN;
    const int* cs = g_csrc;                       // flat positions
    const float* elr = g_el + (size_t)r * NN;
    const float4* x4 = (const float4*)x;

    int st = rp[d], en = rp[d + 1];
    float ax = 0.f, ay = 0.f, az = 0.f, aw = 0.f;
    float den = 0.f;
    if (st < en) {
        float er_d = g_er[(size_t)r * NN + d];
        for (int base = st; base < en; base += 32) {
            int c = en - base;
            if (c > 32) c = 32;
            float w = 0.f;
            int s = 0;
            if (lane < c) {
                s = cs[base + lane];
                float v = elr[s] + er_d;
                v = v > 0.f ? v : 0.2f * v;
                w = expf(v);
            }
            float ws = w;
#pragma unroll
            for (int off = 16; off; off >>= 1)
                ws += __shfl_xor_sync(F, ws, off);
            den += ws;
            for (int j = 0; j < c; j++) {
                float wj = __shfl_sync(F, w, j);
                int sj = __shfl_sync(F, s, j);
                float4 xv = x4[(size_t)sj * 32 + lane];
                ax += wj * xv.x;
                ay += wj * xv.y;
                az += wj * xv.z;
                aw += wj * xv.w;
            }
        }
        float inv = 1.f / den;
        ax *= inv; ay *= inv; az *= inv; aw *= inv;
    }
    __nv_bfloat16 h0 = __float2bfloat16_rn(ax);
    __nv_bfloat16 h1 = __float2bfloat16_rn(ay);
    __nv_bfloat16 h2 = __float2bfloat16_rn(az);
    __nv_bfloat16 h3 = __float2bfloat16_rn(aw);
    __nv_bfloat16 l0 = __float2bfloat16_rn(ax - __bfloat162float(h0));
    __nv_bfloat16 l1 = __float2bfloat16_rn(ay - __bfloat162float(h1));
    __nv_bfloat16 l2 = __float2bfloat16_rn(az - __bfloat162float(h2));
    __nv_bfloat16 l3 = __float2bfloat16_rn(aw - __bfloat162float(h3));
    size_t off = ((size_t)r * NN + d) * DD + lane * 4;
    __stcs((uint2*)(g_yhi + off), make_uint2(pack_bf2(h0, h1), pack_bf2(h2, h3)));
    __stcs((uint2*)(g_ylo + off), make_uint2(pack_bf2(l0, l1), pack_bf2(l2, l3)));
}

// =================== HMMA GEMM (R11-proven, MTILE=64) ======================
#define PAD 136
#define MTILE 64

#define SA_HI 0
#define SA_LO (MTILE * PAD * 2)
#define SB_HI (2 * MTILE * PAD * 2)
#define SB_LO (SB_HI + 128 * PAD * 2)
#define SM_TOTAL (SB_LO + 128 * PAD * 2)   // 104448

__device__ __forceinline__ void mma_bf16(float* c, const uint32_t* a,
                                         const uint32_t* b) {
    asm volatile(
        "mma.sync.aligned.m16n8k16.row.col.f32.bf16.bf16.f32 "
        "{%0,%1,%2,%3}, {%4,%5,%6,%7}, {%8,%9}, {%0,%1,%2,%3};"
        : "+f"(c[0]), "+f"(c[1]), "+f"(c[2]), "+f"(c[3])
        : "r"(a[0]), "r"(a[1]), "r"(a[2]), "r"(a[3]), "r"(b[0]), "r"(b[1]));
}

__global__ void __launch_bounds__(256, 2)
gemm_agg_kernel(float* __restrict__ out, const float* __restrict__ bias,
                int relu,
                const __nv_bfloat16* __restrict__ whiL,
                const __nv_bfloat16* __restrict__ wloL) {
    extern __shared__ char smem[];
    __nv_bfloat16* Ahi = (__nv_bfloat16*)(smem + SA_HI);
    __nv_bfloat16* Alo = (__nv_bfloat16*)(smem + SA_LO);
    __nv_bfloat16* Bhi = (__nv_bfloat16*)(smem + SB_HI);
    __nv_bfloat16* Blo = (__nv_bfloat16*)(smem + SB_LO);

    int tid = threadIdx.x;
    int wid = tid >> 5;
    int lane = tid & 31;
    int m0 = blockIdx.x * MTILE;

    int wm = (wid >> 2) * 32;
    int wn = (wid & 3) * 32;
    int g4 = lane >> 2;
    int l4 = (lane & 3) * 2;

    float acc[2][4][4];
#pragma unroll
    for (int mt = 0; mt < 2; mt++)
#pragma unroll
        for (int nt = 0; nt < 4; nt++)
#pragma unroll
            for (int j = 0; j < 4; j++) acc[mt][nt][j] = 0.f;

    for (int r = 0; r < NR; r++) {
        __syncthreads();

        const uint4* whi4 = (const uint4*)(whiL + (size_t)r * DD * DD);
        const uint4* wlo4 = (const uint4*)(wloL + (size_t)r * DD * DD);
        const uint4* yhi4 = (const uint4*)g_yhi;
        const uint4* ylo4 = (const uint4*)g_ylo;
#pragma unroll
        for (int it = 0; it < 8; it++) {
            int idx = tid + it * 256;
            int row = idx >> 4, c8 = idx & 15;
            *(uint4*)(Bhi + row * PAD + c8 * 8) = whi4[idx];
            *(uint4*)(Blo + row * PAD + c8 * 8) = wlo4[idx];
        }
#pragma unroll
        for (int it = 0; it < 4; it++) {
            int idx = tid + it * 256;
            int row = idx >> 4, c8 = idx & 15;
            uint4 vhi = make_uint4(0, 0, 0, 0), vlo = make_uint4(0, 0, 0, 0);
            if (m0 + row < NN) {
                size_t gi = ((size_t)r * NN + m0 + row) * 16 + c8;
                vhi = __ldcs(&yhi4[gi]);
                vlo = __ldcs(&ylo4[gi]);
            }
            *(uint4*)(Ahi + row * PAD + c8 * 8) = vhi;
            *(uint4*)(Alo + row * PAD + c8 * 8) = vlo;
        }
        __syncthreads();

#pragma unroll
        for (int kk = 0; kk < 8; kk++) {
            int k = kk * 16;
            uint32_t ahi[2][4], alo[2][4];
#pragma unroll
            for (int mt = 0; mt < 2; mt++) {
                int r0 = wm + mt * 16 + g4;
                const __nv_bfloat16* ph = Ahi + r0 * PAD + k + l4;
                const __nv_bfloat16* pl = Alo + r0 * PAD + k + l4;
                ahi[mt][0] = *(const uint32_t*)(ph);
                ahi[mt][1] = *(const uint32_t*)(ph + 8 * PAD);
                ahi[mt][2] = *(const uint32_t*)(ph + 8);
                ahi[mt][3] = *(const uint32_t*)(ph + 8 * PAD + 8);
                alo[mt][0] = *(const uint32_t*)(pl);
                alo[mt][1] = *(const uint32_t*)(pl + 8 * PAD);
                alo[mt][2] = *(const uint32_t*)(pl + 8);
                alo[mt][3] = *(const uint32_t*)(pl + 8 * PAD + 8);
            }
            uint32_t bhi[4][2], blo[4][2];
#pragma unroll
            for (int nt = 0; nt < 4; nt++) {
                int n = wn + nt * 8 + g4;
                const __nv_bfloat16* ph = Bhi + n * PAD + k + l4;
                const __nv_bfloat16* pl = Blo + n * PAD + k + l4;
                bhi[nt][0] = *(const uint32_t*)(ph);
                bhi[nt][1] = *(const uint32_t*)(ph + 8);
                blo[nt][0] = *(const uint32_t*)(pl);
                blo[nt][1] = *(const uint32_t*)(pl + 8);
            }
#pragma unroll
            for (int mt = 0; mt < 2; mt++)
#pragma unroll
                for (int nt = 0; nt < 4; nt++) {
                    mma_bf16(acc[mt][nt], ahi[mt], bhi[nt]);
                    mma_bf16(acc[mt][nt], ahi[mt], blo[nt]);
                    mma_bf16(acc[mt][nt], alo[mt], bhi[nt]);
                }
        }
    }

#pragma unroll
    for (int mt = 0; mt < 2; mt++) {
        int row0 = m0 + wm + mt * 16 + g4;
        int row1 = row0 + 8;
#pragma unroll
        for (int nt = 0; nt < 4; nt++) {
            int col = wn + nt * 8 + l4;
            float b0 = bias[col], b1 = bias[col + 1];
            float v0 = acc[mt][nt][0] + b0, v1 = acc[mt][nt][1] + b1;
            float v2 = acc[mt][nt][2] + b0, v3 = acc[mt][nt][3] + b1;
            if (relu) {
                v0 = fmaxf(v0, 0.f); v1 = fmaxf(v1, 0.f);
                v2 = fmaxf(v2, 0.f); v3 = fmaxf(v3, 0.f);
            }
            if (row0 < NN)
                __stcs((float2*)(out + (size_t)row0 * DD + col),
                       make_float2(v0, v1));
            if (row1 < NN)
                __stcs((float2*)(out + (size_t)row1 * DD + col),
                       make_float2(v2, v3));
        }
    }
}

// ===========================================================================
extern "C" void kernel_launch(void* const* d_in, const int* in_sizes, int n_in,
                              void* d_out, int out_size) {
    const float* h    = (const float*)d_in[0];
    const int*   esrc = (const int*)d_in[1];
    const int*   edst = (const int*)d_in[2];
    const float* fsw  = (const float*)d_in[3];
    const float* fdw  = (const float*)d_in[4];
    const float* al   = (const float*)d_in[5];
    const float* ar   = (const float*)d_in[6];
    const float* hb   = (const float*)d_in[7];
    float* out_final  = (float*)d_out;

    float *bufA, *bufB, *vl, *vr;
    __nv_bfloat16 *whi, *wlo;
    cudaGetSymbolAddress((void**)&bufA, g_bufA);
    cudaGetSymbolAddress((void**)&bufB, g_bufB);
    cudaGetSymbolAddress((void**)&vl,   g_vl);
    cudaGetSymbolAddress((void**)&vr,   g_vr);
    cudaGetSymbolAddress((void**)&whi,  g_whi);
    cudaGetSymbolAddress((void**)&wlo,  g_wlo);

    cudaFuncSetAttribute(gemm_agg_kernel,
                         cudaFuncAttributeMaxDynamicSharedMemorySize, SM_TOTAL);

    const int MT = (NN + MTILE - 1) / MTILE;   // 1563

    // 1: histogram (+ scan-state reset in tail blocks)
    hist_kernel<<<NR * FILLB + 7, 256>>>(edst);
    // 2: lookback scan + all-layer W prep + all-layer vecs
    scan_prep_kernel<<<SNB + 768 + 48, 512>>>(fsw, fdw, al, ar);
    // 3: CSR fill + layer-0 scores
    fill_scores_kernel<<<NR * FILLB + NN / 32, 256>>>(esrc, edst, h, vl, vr);

    const float* x = h;
    for (int l = 0; l < NL; l++) {
        float* out = (l == 0) ? bufB : (l == 1) ? bufA : out_final;

        if (l > 0)
            scores_kernel<<<NN / 32, 256>>>(x, vl + l * NR * DD,
                                            vr + l * NR * DD);
        agg_kernel<<<dim3((NN + 7) / 8, NR), 256>>>(x);   // 4th kernel (l=0)
        gemm_agg_kernel<<<MT, 256, SM_TOTAL>>>(out, hb + l * DD,
                                               l < NL - 1 ? 1 : 0,
                                               whi + (size_t)l * NR * DD * DD,
                                               wlo + (size_t)l * NR * DD * DD);
        x = out;
    }
}

// round 14
// speedup vs baseline: 1.8140x; 1.1393x over previous
#include <cuda_runtime.h>
#include <cuda_bf16.h>
#include <math.h>
#include <cstdint>

#define NN 100000
#define NR 8
#define NE 400000
#define DD 128
#define NL 3

#define SNB 1563                 // scan blocks: ceil(800000/512)
#define FILLB 1563               // fill blocks per relation: ceil(NE/256)

// ---------------- device scratch (static, no allocations) ----------------
__device__ float         g_bufA[NN * DD];
__device__ float         g_bufB[NN * DD];
__device__ float         g_el[NR * NN];
__device__ float         g_er[NR * NN];
__device__ float         g_vl[NL * NR * DD];
__device__ float         g_vr[NL * NR * DD];
__device__ __nv_bfloat16 g_whi[(size_t)NL * NR * DD * DD];
__device__ __nv_bfloat16 g_wlo[(size_t)NL * NR * DD * DD];
__device__ __nv_bfloat16 g_yhi[(size_t)NR * NN * DD];
__device__ __nv_bfloat16 g_ylo[(size_t)NR * NN * DD];
__device__ int           g_cnt[NR * NN];       // zero at start; reset by scan
__device__ int           g_fill[NR * NN];      // reset by scan
__device__ int           g_rowptrF[NR * NN + 1];
__device__ int           g_csrc[(size_t)NR * NE];
__device__ int           g_cdst[(size_t)NR * NE];
__device__ uint2         g_ws[(size_t)NR * NE];   // (w, src) per CSR slot
__device__ int           g_state[SNB];         // lookback: (value<<2)|flag
__device__ int           g_ticket;

// =================== kernel 1: hist + scan-state reset =====================
__global__ void hist_kernel(const int* __restrict__ edst) {
    int b = blockIdx.x;
    int tid = threadIdx.x;
    if (b < NR * FILLB) {
        int r = b / FILLB;
        int i = (b % FILLB) * 256 + tid;
        if (i < NE) {
            int d = edst[(size_t)r * NE + i];
            atomicAdd(&g_cnt[r * NN + d], 1);
        }
    } else {
        int i = (b - NR * FILLB) * 256 + tid;
        if (i < SNB) g_state[i] = 0;
        if (i == 0) g_ticket = 0;
    }
}

// =================== kernel 2: lookback scan + W prep + vecs ===============
__global__ void __launch_bounds__(512)
scan_prep_kernel(const float* __restrict__ fsw,
                 const float* __restrict__ fdw,
                 const float* __restrict__ al,
                 const float* __restrict__ ar) {
    int b = blockIdx.x;
    int tid = threadIdx.x;
    if (b < SNB) {
        __shared__ int sh[512];
        __shared__ int sbc[2];
        if (tid == 0) sbc[0] = atomicAdd(&g_ticket, 1);
        __syncthreads();
        int vid = sbc[0];
        int e = vid * 512 + tid;
        int v = 0;
        if (e < NR * NN) {
            v = g_cnt[e];
            g_cnt[e] = 0;
            g_fill[e] = 0;
        }
        sh[tid] = v;
        __syncthreads();
#pragma unroll
        for (int off = 1; off < 512; off <<= 1) {
            int t = (tid >= off) ? sh[tid - off] : 0;
            __syncthreads();
            sh[tid] += t;
            __syncthreads();
        }
        int incl = sh[tid];
        int btot = sh[511];
        if (tid == 0) {
            atomicExch(&g_state[vid], (btot << 2) | 1);
            int run = 0;
            int p = vid - 1;
            while (p >= 0) {
                int w = atomicAdd(&g_state[p], 0);
                int f = w & 3;
                if (f == 0) continue;
                run += (w >> 2);
                if (f == 2) break;
                p--;
            }
            atomicExch(&g_state[vid], ((run + btot) << 2) | 2);
            sbc[1] = run;
            if (vid == SNB - 1) {
                g_rowptrF[NR * NN] = run + btot;
                g_ticket = 0;
            }
        }
        __syncthreads();
        int run = sbc[1];
        if (e < NR * NN) g_rowptrF[e] = run + incl - v;
    } else if (b < SNB + 768) {
        int i = (b - SNB) * 512 + tid;
        float v = fsw[i];
        __nv_bfloat16 hi = __float2bfloat16_rn(v);
        g_whi[i] = hi;
        g_wlo[i] = __float2bfloat16_rn(v - __bfloat162float(hi));
    } else if (tid < 128) {
        int bb = b - SNB - 768;       // 0..47
        int l = bb >> 4;
        int sub = bb & 15;
        int r = sub >> 1;
        size_t wo = ((size_t)l * NR + r) * DD * DD;
        const float* W = (sub & 1) ? (fdw + wo) : (fsw + wo);
        const float* a = ((sub & 1) ? ar : al) + (l * NR + r) * DD;
        int k = tid;
        float s = 0.f;
#pragma unroll 8
        for (int j = 0; j < DD; j++) s += a[j] * W[j * DD + k];
        float* o = (sub & 1) ? g_vr : g_vl;
        o[(l * NR + r) * DD + k] = s;
    }
}

// -------- scores block body (256 threads) ----------------------------------
__device__ __forceinline__ void scores_block(const float* __restrict__ x,
                                             const float* __restrict__ vl,
                                             const float* __restrict__ vr,
                                             int n0) {
    __shared__ float xs[32][133];
    __shared__ float vv[16][DD];
    int tid = threadIdx.x;
    for (int i = tid; i < 16 * DD; i += 256) {
        int v = i >> 7, k = i & 127;
        vv[v][k] = (v < 8) ? vl[v * DD + k] : vr[(v - 8) * DD + k];
    }
    for (int i = tid; i < 32 * DD; i += 256) {
        int r = i >> 7, k = i & 127;
        xs[r][k] = x[(size_t)(n0 + r) * DD + k];
    }
    __syncthreads();

    int node = tid & 31;
    int v0 = (tid >> 5) * 2;
    float a0 = 0.f, a1 = 0.f;
#pragma unroll 8
    for (int k = 0; k < DD; k++) {
        float xv = xs[node][k];
        a0 += xv * vv[v0][k];
        a1 += xv * vv[v0 + 1][k];
    }
    int n = n0 + node;
    if (v0 < 8) g_el[v0 * NN + n] = a0;
    else        g_er[(v0 - 8) * NN + n] = a0;
    int v1 = v0 + 1;
    if (v1 < 8) g_el[v1 * NN + n] = a1;
    else        g_er[(v1 - 8) * NN + n] = a1;
}

// =================== kernel 3: CSR fill (+cdst) + layer-0 scores ===========
__global__ void __launch_bounds__(256)
fill_scores_kernel(const int* __restrict__ esrc,
                   const int* __restrict__ edst,
                   const float* __restrict__ x,
                   const float* __restrict__ vl0,
                   const float* __restrict__ vr0) {
    int b = blockIdx.x;
    if (b < NR * FILLB) {
        int r = b / FILLB;
        int i = (b % FILLB) * 256 + threadIdx.x;
        if (i < NE) {
            int d = edst[(size_t)r * NE + i];
            int s = esrc[(size_t)r * NE + i];
            int pos = g_rowptrF[r * NN + d] + atomicAdd(&g_fill[r * NN + d], 1);
            g_csrc[pos] = s;
            g_cdst[pos] = d;
        }
    } else {
        scores_block(x, vl0, vr0, (b - NR * FILLB) * 32);
    }
}

// =================== standalone scores (layers 1,2) ========================
__global__ void __launch_bounds__(256)
scores_kernel(const float* __restrict__ x,
              const float* __restrict__ vl,
              const float* __restrict__ vr) {
    scores_block(x, vl, vr, blockIdx.x * 32);
}

// =================== alpha: w = exp(leaky(el[s]+er[d])) per CSR slot =======
__global__ void __launch_bounds__(256)
alpha_kernel() {
    int i = blockIdx.x * 256 + threadIdx.x;
    if (i >= NR * NE) return;
    int r = i / NE;
    int s = g_csrc[i];
    int d = g_cdst[i];
    float v = g_el[(size_t)r * NN + s] + g_er[(size_t)r * NN + d];
    v = v > 0.f ? v : 0.2f * v;
    float w = expf(v);
    g_ws[i] = make_uint2(__float_as_uint(w), (unsigned)s);
}

// =================== aggregation: shfl-free uniform-load inner loop ========
__device__ __forceinline__ uint32_t pack_bf2(__nv_bfloat16 a, __nv_bfloat16 b) {
    return (uint32_t)__bfloat16_as_ushort(a) |
           ((uint32_t)__bfloat16_as_ushort(b) << 16);
}

__global__ void __launch_bounds__(256)
agg_kernel(const float* __restrict__ x) {
    int lane = threadIdx.x & 31;
    int d = blockIdx.x * 8 + (threadIdx.x >> 5);
    int r = blockIdx.y;
    if (d >= NN) return;

    const int* rp = g_rowptrF + (size_t)r * NN;
    const uint2* ws = g_ws;
    const float4* x4 = (const float4*)x;

    int st = rp[d], en = rp[d + 1];
    float ax = 0.f, ay = 0.f, az = 0.f, aw = 0.f;
    float den = 0.f;
    for (int e = st; e < en; e++) {
        uint2 p = ws[e];                  // uniform across warp -> broadcast
        float w = __uint_as_float(p.x);
        int s = (int)p.y;
        den += w;                         // same value in every lane
        float4 xv = x4[(size_t)s * 32 + lane];
        ax += w * xv.x;
        ay += w * xv.y;
        az += w * xv.z;
        aw += w * xv.w;
    }
    float inv = den > 0.f ? 1.f / den : 0.f;
    ax *= inv; ay *= inv; az *= inv; aw *= inv;

    __nv_bfloat16 h0 = __float2bfloat16_rn(ax);
    __nv_bfloat16 h1 = __float2bfloat16_rn(ay);
    __nv_bfloat16 h2 = __float2bfloat16_rn(az);
    __nv_bfloat16 h3 = __float2bfloat16_rn(aw);
    __nv_bfloat16 l0 = __float2bfloat16_rn(ax - __bfloat162float(h0));
    __nv_bfloat16 l1 = __float2bfloat16_rn(ay - __bfloat162float(h1));
    __nv_bfloat16 l2 = __float2bfloat16_rn(az - __bfloat162float(h2));
    __nv_bfloat16 l3 = __float2bfloat16_rn(aw - __bfloat162float(h3));
    size_t off = ((size_t)r * NN + d) * DD + lane * 4;
    __stcs((uint2*)(g_yhi + off), make_uint2(pack_bf2(h0, h1), pack_bf2(h2, h3)));
    __stcs((uint2*)(g_ylo + off), make_uint2(pack_bf2(l0, l1), pack_bf2(l2, l3)));
}

// =================== HMMA GEMM (R11-proven, MTILE=64) ======================
#define PAD 136
#define MTILE 64

#define SA_HI 0
#define SA_LO (MTILE * PAD * 2)
#define SB_HI (2 * MTILE * PAD * 2)
#define SB_LO (SB_HI + 128 * PAD * 2)
#define SM_TOTAL (SB_LO + 128 * PAD * 2)   // 104448

__device__ __forceinline__ void mma_bf16(float* c, const uint32_t* a,
                                         const uint32_t* b) {
    asm volatile(
        "mma.sync.aligned.m16n8k16.row.col.f32.bf16.bf16.f32 "
        "{%0,%1,%2,%3}, {%4,%5,%6,%7}, {%8,%9}, {%0,%1,%2,%3};"
        : "+f"(c[0]), "+f"(c[1]), "+f"(c[2]), "+f"(c[3])
        : "r"(a[0]), "r"(a[1]), "r"(a[2]), "r"(a[3]), "r"(b[0]), "r"(b[1]));
}

__global__ void __launch_bounds__(256, 2)
gemm_agg_kernel(float* __restrict__ out, const float* __restrict__ bias,
                int relu,
                const __nv_bfloat16* __restrict__ whiL,
                const __nv_bfloat16* __restrict__ wloL) {
    extern __shared__ char smem[];
    __nv_bfloat16* Ahi = (__nv_bfloat16*)(smem + SA_HI);
    __nv_bfloat16* Alo = (__nv_bfloat16*)(smem + SA_LO);
    __nv_bfloat16* Bhi = (__nv_bfloat16*)(smem + SB_HI);
    __nv_bfloat16* Blo = (__nv_bfloat16*)(smem + SB_LO);

    int tid = threadIdx.x;
    int wid = tid >> 5;
    int lane = tid & 31;
    int m0 = blockIdx.x * MTILE;

    int wm = (wid >> 2) * 32;
    int wn = (wid & 3) * 32;
    int g4 = lane >> 2;
    int l4 = (lane & 3) * 2;

    float acc[2][4][4];
#pragma unroll
    for (int mt = 0; mt < 2; mt++)
#pragma unroll
        for (int nt = 0; nt < 4; nt++)
#pragma unroll
            for (int j = 0; j < 4; j++) acc[mt][nt][j] = 0.f;

    for (int r = 0; r < NR; r++) {
        __syncthreads();

        const uint4* whi4 = (const uint4*)(whiL + (size_t)r * DD * DD);
        const uint4* wlo4 = (const uint4*)(wloL + (size_t)r * DD * DD);
        const uint4* yhi4 = (const uint4*)g_yhi;
        const uint4* ylo4 = (const uint4*)g_ylo;
#pragma unroll
        for (int it = 0; it < 8; it++) {
            int idx = tid + it * 256;
            int row = idx >> 4, c8 = idx & 15;
            *(uint4*)(Bhi + row * PAD + c8 * 8) = whi4[idx];
            *(uint4*)(Blo + row * PAD + c8 * 8) = wlo4[idx];
        }
#pragma unroll
        for (int it = 0; it < 4; it++) {
            int idx = tid + it * 256;
            int row = idx >> 4, c8 = idx & 15;
            uint4 vhi = make_uint4(0, 0, 0, 0), vlo = make_uint4(0, 0, 0, 0);
            if (m0 + row < NN) {
                size_t gi = ((size_t)r * NN + m0 + row) * 16 + c8;
                vhi = __ldcs(&yhi4[gi]);
                vlo = __ldcs(&ylo4[gi]);
            }
            *(uint4*)(Ahi + row * PAD + c8 * 8) = vhi;
            *(uint4*)(Alo + row * PAD + c8 * 8) = vlo;
        }
        __syncthreads();

#pragma unroll
        for (int kk = 0; kk < 8; kk++) {
            int k = kk * 16;
            uint32_t ahi[2][4], alo[2][4];
#pragma unroll
            for (int mt = 0; mt < 2; mt++) {
                int r0 = wm + mt * 16 + g4;
                const __nv_bfloat16* ph = Ahi + r0 * PAD + k + l4;
                const __nv_bfloat16* pl = Alo + r0 * PAD + k + l4;
                ahi[mt][0] = *(const uint32_t*)(ph);
                ahi[mt][1] = *(const uint32_t*)(ph + 8 * PAD);
                ahi[mt][2] = *(const uint32_t*)(ph + 8);
                ahi[mt][3] = *(const uint32_t*)(ph + 8 * PAD + 8);
                alo[mt][0] = *(const uint32_t*)(pl);
                alo[mt][1] = *(const uint32_t*)(pl + 8 * PAD);
                alo[mt][2] = *(const uint32_t*)(pl + 8);
                alo[mt][3] = *(const uint32_t*)(pl + 8 * PAD + 8);
            }
            uint32_t bhi[4][2], blo[4][2];
#pragma unroll
            for (int nt = 0; nt < 4; nt++) {
                int n = wn + nt * 8 + g4;
                const __nv_bfloat16* ph = Bhi + n * PAD + k + l4;
                const __nv_bfloat16* pl = Blo + n * PAD + k + l4;
                bhi[nt][0] = *(const uint32_t*)(ph);
                bhi[nt][1] = *(const uint32_t*)(ph + 8);
                blo[nt][0] = *(const uint32_t*)(pl);
                blo[nt][1] = *(const uint32_t*)(pl + 8);
            }
#pragma unroll
            for (int mt = 0; mt < 2; mt++)
#pragma unroll
                for (int nt = 0; nt < 4; nt++) {
                    mma_bf16(acc[mt][nt], ahi[mt], bhi[nt]);
                    mma_bf16(acc[mt][nt], ahi[mt], blo[nt]);
                    mma_bf16(acc[mt][nt], alo[mt], bhi[nt]);
                }
        }
    }

#pragma unroll
    for (int mt = 0; mt < 2; mt++) {
        int row0 = m0 + wm + mt * 16 + g4;
        int row1 = row0 + 8;
#pragma unroll
        for (int nt = 0; nt < 4; nt++) {
            int col = wn + nt * 8 + l4;
            float b0 = bias[col], b1 = bias[col + 1];
            float v0 = acc[mt][nt][0] + b0, v1 = acc[mt][nt][1] + b1;
            float v2 = acc[mt][nt][2] + b0, v3 = acc[mt][nt][3] + b1;
            if (relu) {
                v0 = fmaxf(v0, 0.f); v1 = fmaxf(v1, 0.f);
                v2 = fmaxf(v2, 0.f); v3 = fmaxf(v3, 0.f);
            }
            if (row0 < NN)
                __stcs((float2*)(out + (size_t)row0 * DD + col),
                       make_float2(v0, v1));
            if (row1 < NN)
                __stcs((float2*)(out + (size_t)row1 * DD + col),
                       make_float2(v2, v3));
        }
    }
}

// ===========================================================================
extern "C" void kernel_launch(void* const* d_in, const int* in_sizes, int n_in,
                              void* d_out, int out_size) {
    const float* h    = (const float*)d_in[0];
    const int*   esrc = (const int*)d_in[1];
    const int*   edst = (const int*)d_in[2];
    const float* fsw  = (const float*)d_in[3];
    const float* fdw  = (const float*)d_in[4];
    const float* al   = (const float*)d_in[5];
    const float* ar   = (const float*)d_in[6];
    const float* hb   = (const float*)d_in[7];
    float* out_final  = (float*)d_out;

    float *bufA, *bufB, *vl, *vr;
    __nv_bfloat16 *whi, *wlo;
    cudaGetSymbolAddress((void**)&bufA, g_bufA);
    cudaGetSymbolAddress((void**)&bufB, g_bufB);
    cudaGetSymbolAddress((void**)&vl,   g_vl);
    cudaGetSymbolAddress((void**)&vr,   g_vr);
    cudaGetSymbolAddress((void**)&whi,  g_whi);
    cudaGetSymbolAddress((void**)&wlo,  g_wlo);

    cudaFuncSetAttribute(gemm_agg_kernel,
                         cudaFuncAttributeMaxDynamicSharedMemorySize, SM_TOTAL);

    const int MT = (NN + MTILE - 1) / MTILE;   // 1563
    const int AB = (NR * NE + 255) / 256;      // 12500

    // 1: histogram (+ scan-state reset in tail blocks)
    hist_kernel<<<NR * FILLB + 7, 256>>>(edst);
    // 2: lookback scan + all-layer W prep + all-layer vecs
    scan_prep_kernel<<<SNB + 768 + 48, 512>>>(fsw, fdw, al, ar);
    // 3: CSR fill (+cdst) + layer-0 scores
    fill_scores_kernel<<<NR * FILLB + NN / 32, 256>>>(esrc, edst, h, vl, vr);

    const float* x = h;
    for (int l = 0; l < NL; l++) {
        float* out = (l == 0) ? bufB : (l == 1) ? bufA : out_final;

        if (l > 0)
            scores_kernel<<<NN / 32, 256>>>(x, vl + l * NR * DD,
                                            vr + l * NR * DD);
        alpha_kernel<<<AB, 256>>>();                      // 4th kernel (l=0)
        agg_kernel<<<dim3((NN + 7) / 8, NR), 256>>>(x);
        gemm_agg_kernel<<<MT, 256, SM_TOTAL>>>(out, hb + l * DD,
                                               l < NL - 1 ? 1 : 0,
                                               whi + (size_t)l * NR * DD * DD,
                                               wlo + (size_t)l * NR * DD * DD);
        x = out;
    }
}

// round 15
// speedup vs baseline: 1.8472x; 1.0183x over previous
#include <cuda_runtime.h>
#include <cuda_bf16.h>
#include <math.h>
#include <cstdint>

#define NN 100000
#define NR 8
#define NE 400000
#define DD 128
#define NL 3

#define SNB 1563                 // scan blocks: ceil(800000/512)
#define FILLB 1563               // fill blocks per relation: ceil(NE/256)

// ---------------- device scratch (static, no allocations) ----------------
__device__ float         g_bufA[NN * DD];
__device__ float         g_bufB[NN * DD];
__device__ float         g_el[NR * NN];
__device__ float         g_er[NR * NN];
__device__ float         g_vl[NL * NR * DD];
__device__ float         g_vr[NL * NR * DD];
__device__ __nv_bfloat16 g_whi[(size_t)NL * NR * DD * DD];
__device__ __nv_bfloat16 g_wlo[(size_t)NL * NR * DD * DD];
__device__ __nv_bfloat16 g_yhi[(size_t)NR * NN * DD];
__device__ __nv_bfloat16 g_ylo[(size_t)NR * NN * DD];
__device__ int           g_cnt[NR * NN];       // zero at start; reset by scan
__device__ int           g_fill[NR * NN];      // reset by scan
__device__ int           g_rowptrF[NR * NN + 1];
__device__ int           g_csrc[(size_t)NR * NE];
__device__ int           g_cdst[(size_t)NR * NE];
__device__ uint2         g_ws[(size_t)NR * NE];   // (w, src) per CSR slot
__device__ int           g_state[SNB];         // lookback: (value<<2)|flag
__device__ int           g_ticket;

// =================== kernel 1: hist + scan-state reset =====================
__global__ void hist_kernel(const int* __restrict__ edst) {
    int b = blockIdx.x;
    int tid = threadIdx.x;
    if (b < NR * FILLB) {
        int r = b / FILLB;
        int i = (b % FILLB) * 256 + tid;
        if (i < NE) {
            int d = edst[(size_t)r * NE + i];
            atomicAdd(&g_cnt[r * NN + d], 1);
        }
    } else {
        int i = (b - NR * FILLB) * 256 + tid;
        if (i < SNB) g_state[i] = 0;
        if (i == 0) g_ticket = 0;
    }
}

// =================== kernel 2: lookback scan + W prep + vecs ===============
__global__ void __launch_bounds__(512)
scan_prep_kernel(const float* __restrict__ fsw,
                 const float* __restrict__ fdw,
                 const float* __restrict__ al,
                 const float* __restrict__ ar) {
    int b = blockIdx.x;
    int tid = threadIdx.x;
    if (b < SNB) {
        __shared__ int sh[512];
        __shared__ int sbc[2];
        if (tid == 0) sbc[0] = atomicAdd(&g_ticket, 1);
        __syncthreads();
        int vid = sbc[0];
        int e = vid * 512 + tid;
        int v = 0;
        if (e < NR * NN) {
            v = g_cnt[e];
            g_cnt[e] = 0;
            g_fill[e] = 0;
        }
        sh[tid] = v;
        __syncthreads();
#pragma unroll
        for (int off = 1; off < 512; off <<= 1) {
            int t = (tid >= off) ? sh[tid - off] : 0;
            __syncthreads();
            sh[tid] += t;
            __syncthreads();
        }
        int incl = sh[tid];
        int btot = sh[511];
        if (tid == 0) {
            atomicExch(&g_state[vid], (btot << 2) | 1);
            int run = 0;
            int p = vid - 1;
            while (p >= 0) {
                int w = atomicAdd(&g_state[p], 0);
                int f = w & 3;
                if (f == 0) continue;
                run += (w >> 2);
                if (f == 2) break;
                p--;
            }
            atomicExch(&g_state[vid], ((run + btot) << 2) | 2);
            sbc[1] = run;
            if (vid == SNB - 1) {
                g_rowptrF[NR * NN] = run + btot;
                g_ticket = 0;
            }
        }
        __syncthreads();
        int run = sbc[1];
        if (e < NR * NN) g_rowptrF[e] = run + incl - v;
    } else if (b < SNB + 768) {
        int i = (b - SNB) * 512 + tid;
        float v = fsw[i];
        __nv_bfloat16 hi = __float2bfloat16_rn(v);
        g_whi[i] = hi;
        g_wlo[i] = __float2bfloat16_rn(v - __bfloat162float(hi));
    } else if (tid < 128) {
        int bb = b - SNB - 768;       // 0..47
        int l = bb >> 4;
        int sub = bb & 15;
        int r = sub >> 1;
        size_t wo = ((size_t)l * NR + r) * DD * DD;
        const float* W = (sub & 1) ? (fdw + wo) : (fsw + wo);
        const float* a = ((sub & 1) ? ar : al) + (l * NR + r) * DD;
        int k = tid;
        float s = 0.f;
#pragma unroll 8
        for (int j = 0; j < DD; j++) s += a[j] * W[j * DD + k];
        float* o = (sub & 1) ? g_vr : g_vl;
        o[(l * NR + r) * DD + k] = s;
    }
}

// -------- scores block body (256 threads) ----------------------------------
__device__ __forceinline__ void scores_block(const float* __restrict__ x,
                                             const float* __restrict__ vl,
                                             const float* __restrict__ vr,
                                             int n0) {
    __shared__ float xs[32][133];
    __shared__ float vv[16][DD];
    int tid = threadIdx.x;
    for (int i = tid; i < 16 * DD; i += 256) {
        int v = i >> 7, k = i & 127;
        vv[v][k] = (v < 8) ? vl[v * DD + k] : vr[(v - 8) * DD + k];
    }
    for (int i = tid; i < 32 * DD; i += 256) {
        int r = i >> 7, k = i & 127;
        xs[r][k] = x[(size_t)(n0 + r) * DD + k];
    }
    __syncthreads();

    int node = tid & 31;
    int v0 = (tid >> 5) * 2;
    float a0 = 0.f, a1 = 0.f;
#pragma unroll 8
    for (int k = 0; k < DD; k++) {
        float xv = xs[node][k];
        a0 += xv * vv[v0][k];
        a1 += xv * vv[v0 + 1][k];
    }
    int n = n0 + node;
    if (v0 < 8) g_el[v0 * NN + n] = a0;
    else        g_er[(v0 - 8) * NN + n] = a0;
    int v1 = v0 + 1;
    if (v1 < 8) g_el[v1 * NN + n] = a1;
    else        g_er[(v1 - 8) * NN + n] = a1;
}

// =================== kernel 3: CSR fill (+cdst) + layer-0 scores ===========
__global__ void __launch_bounds__(256)
fill_scores_kernel(const int* __restrict__ esrc,
                   const int* __restrict__ edst,
                   const float* __restrict__ x,
                   const float* __restrict__ vl0,
                   const float* __restrict__ vr0) {
    int b = blockIdx.x;
    if (b < NR * FILLB) {
        int r = b / FILLB;
        int i = (b % FILLB) * 256 + threadIdx.x;
        if (i < NE) {
            int d = edst[(size_t)r * NE + i];
            int s = esrc[(size_t)r * NE + i];
            int pos = g_rowptrF[r * NN + d] + atomicAdd(&g_fill[r * NN + d], 1);
            g_csrc[pos] = s;
            g_cdst[pos] = d;
        }
    } else {
        scores_block(x, vl0, vr0, (b - NR * FILLB) * 32);
    }
}

// =================== standalone scores (layers 1,2) ========================
__global__ void __launch_bounds__(256)
scores_kernel(const float* __restrict__ x,
              const float* __restrict__ vl,
              const float* __restrict__ vr) {
    scores_block(x, vl, vr, blockIdx.x * 32);
}

// =================== alpha: w = exp(leaky(el[s]+er[d])) per CSR slot =======
__global__ void __launch_bounds__(256)
alpha_kernel() {
    int i = blockIdx.x * 256 + threadIdx.x;
    if (i >= NR * NE) return;
    int r = i / NE;
    int s = g_csrc[i];
    int d = g_cdst[i];
    float v = g_el[(size_t)r * NN + s] + g_er[(size_t)r * NN + d];
    v = v > 0.f ? v : 0.2f * v;
    float w = expf(v);
    g_ws[i] = make_uint2(__float_as_uint(w), (unsigned)s);
}

// =================== aggregation: 2-edge unrolled inner loop (MLP=2) =======
__device__ __forceinline__ uint32_t pack_bf2(__nv_bfloat16 a, __nv_bfloat16 b) {
    return (uint32_t)__bfloat16_as_ushort(a) |
           ((uint32_t)__bfloat16_as_ushort(b) << 16);
}

__global__ void __launch_bounds__(256)
agg_kernel(const float* __restrict__ x) {
    int lane = threadIdx.x & 31;
    int d = blockIdx.x * 8 + (threadIdx.x >> 5);
    int r = blockIdx.y;
    if (d >= NN) return;

    const int* rp = g_rowptrF + (size_t)r * NN;
    const uint2* ws = g_ws;
    const float4* x4 = (const float4*)x;

    int st = rp[d], en = rp[d + 1];
    float ax = 0.f, ay = 0.f, az = 0.f, aw = 0.f;
    float den = 0.f;
    int e = st;
    for (; e + 2 <= en; e += 2) {
        uint2 p0 = ws[e];
        uint2 p1 = ws[e + 1];
        float w0 = __uint_as_float(p0.x);
        float w1 = __uint_as_float(p1.x);
        int s0 = (int)p0.y;
        int s1 = (int)p1.y;
        float4 v0 = x4[(size_t)s0 * 32 + lane];
        float4 v1 = x4[(size_t)s1 * 32 + lane];
        den += w0 + w1;
        ax += w0 * v0.x; ay += w0 * v0.y; az += w0 * v0.z; aw += w0 * v0.w;
        ax += w1 * v1.x; ay += w1 * v1.y; az += w1 * v1.z; aw += w1 * v1.w;
    }
    if (e < en) {
        uint2 p = ws[e];
        float w = __uint_as_float(p.x);
        int s = (int)p.y;
        float4 xv = x4[(size_t)s * 32 + lane];
        den += w;
        ax += w * xv.x; ay += w * xv.y; az += w * xv.z; aw += w * xv.w;
    }
    float inv = den > 0.f ? 1.f / den : 0.f;
    ax *= inv; ay *= inv; az *= inv; aw *= inv;

    __nv_bfloat16 h0 = __float2bfloat16_rn(ax);
    __nv_bfloat16 h1 = __float2bfloat16_rn(ay);
    __nv_bfloat16 h2 = __float2bfloat16_rn(az);
    __nv_bfloat16 h3 = __float2bfloat16_rn(aw);
    __nv_bfloat16 l0 = __float2bfloat16_rn(ax - __bfloat162float(h0));
    __nv_bfloat16 l1 = __float2bfloat16_rn(ay - __bfloat162float(h1));
    __nv_bfloat16 l2 = __float2bfloat16_rn(az - __bfloat162float(h2));
    __nv_bfloat16 l3 = __float2bfloat16_rn(aw - __bfloat162float(h3));
    size_t off = ((size_t)r * NN + d) * DD + lane * 4;
    __stcs((uint2*)(g_yhi + off), make_uint2(pack_bf2(h0, h1), pack_bf2(h2, h3)));
    __stcs((uint2*)(g_ylo + off), make_uint2(pack_bf2(l0, l1), pack_bf2(l2, l3)));
}

// =================== HMMA GEMM (R11-proven, MTILE=64) ======================
#define PAD 136
#define MTILE 64

#define SA_HI 0
#define SA_LO (MTILE * PAD * 2)
#define SB_HI (2 * MTILE * PAD * 2)
#define SB_LO (SB_HI + 128 * PAD * 2)
#define SM_TOTAL (SB_LO + 128 * PAD * 2)   // 104448

__device__ __forceinline__ void mma_bf16(float* c, const uint32_t* a,
                                         const uint32_t* b) {
    asm volatile(
        "mma.sync.aligned.m16n8k16.row.col.f32.bf16.bf16.f32 "
        "{%0,%1,%2,%3}, {%4,%5,%6,%7}, {%8,%9}, {%0,%1,%2,%3};"
        : "+f"(c[0]), "+f"(c[1]), "+f"(c[2]), "+f"(c[3])
        : "r"(a[0]), "r"(a[1]), "r"(a[2]), "r"(a[3]), "r"(b[0]), "r"(b[1]));
}

__global__ void __launch_bounds__(256, 2)
gemm_agg_kernel(float* __restrict__ out, const float* __restrict__ bias,
                int relu,
                const __nv_bfloat16* __restrict__ whiL,
                const __nv_bfloat16* __restrict__ wloL) {
    extern __shared__ char smem[];
    __nv_bfloat16* Ahi = (__nv_bfloat16*)(smem + SA_HI);
    __nv_bfloat16* Alo = (__nv_bfloat16*)(smem + SA_LO);
    __nv_bfloat16* Bhi = (__nv_bfloat16*)(smem + SB_HI);
    __nv_bfloat16* Blo = (__nv_bfloat16*)(smem + SB_LO);

    int tid = threadIdx.x;
    int wid = tid >> 5;
    int lane = tid & 31;
    int m0 = blockIdx.x * MTILE;

    int wm = (wid >> 2) * 32;
    int wn = (wid & 3) * 32;
    int g4 = lane >> 2;
    int l4 = (lane & 3) * 2;

    float acc[2][4][4];
#pragma unroll
    for (int mt = 0; mt < 2; mt++)
#pragma unroll
        for (int nt = 0; nt < 4; nt++)
#pragma unroll
            for (int j = 0; j < 4; j++) acc[mt][nt][j] = 0.f;

    for (int r = 0; r < NR; r++) {
        __syncthreads();

        const uint4* whi4 = (const uint4*)(whiL + (size_t)r * DD * DD);
        const uint4* wlo4 = (const uint4*)(wloL + (size_t)r * DD * DD);
        const uint4* yhi4 = (const uint4*)g_yhi;
        const uint4* ylo4 = (const uint4*)g_ylo;
#pragma unroll
        for (int it = 0; it < 8; it++) {
            int idx = tid + it * 256;
            int row = idx >> 4, c8 = idx & 15;
            *(uint4*)(Bhi + row * PAD + c8 * 8) = whi4[idx];
            *(uint4*)(Blo + row * PAD + c8 * 8) = wlo4[idx];
        }
#pragma unroll
        for (int it = 0; it < 4; it++) {
            int idx = tid + it * 256;
            int row = idx >> 4, c8 = idx & 15;
            uint4 vhi = make_uint4(0, 0, 0, 0), vlo = make_uint4(0, 0, 0, 0);
            if (m0 + row < NN) {
                size_t gi = ((size_t)r * NN + m0 + row) * 16 + c8;
                vhi = __ldcs(&yhi4[gi]);
                vlo = __ldcs(&ylo4[gi]);
            }
            *(uint4*)(Ahi + row * PAD + c8 * 8) = vhi;
            *(uint4*)(Alo + row * PAD + c8 * 8) = vlo;
        }
        __syncthreads();

#pragma unroll
        for (int kk = 0; kk < 8; kk++) {
            int k = kk * 16;
            uint32_t ahi[2][4], alo[2][4];
#pragma unroll
            for (int mt = 0; mt < 2; mt++) {
                int r0 = wm + mt * 16 + g4;
                const __nv_bfloat16* ph = Ahi + r0 * PAD + k + l4;
                const __nv_bfloat16* pl = Alo + r0 * PAD + k + l4;
                ahi[mt][0] = *(const uint32_t*)(ph);
                ahi[mt][1] = *(const uint32_t*)(ph + 8 * PAD);
                ahi[mt][2] = *(const uint32_t*)(ph + 8);
                ahi[mt][3] = *(const uint32_t*)(ph + 8 * PAD + 8);
                alo[mt][0] = *(const uint32_t*)(pl);
                alo[mt][1] = *(const uint32_t*)(pl + 8 * PAD);
                alo[mt][2] = *(const uint32_t*)(pl + 8);
                alo[mt][3] = *(const uint32_t*)(pl + 8 * PAD + 8);
            }
            uint32_t bhi[4][2], blo[4][2];
#pragma unroll
            for (int nt = 0; nt < 4; nt++) {
                int n = wn + nt * 8 + g4;
                const __nv_bfloat16* ph = Bhi + n * PAD + k + l4;
                const __nv_bfloat16* pl = Blo + n * PAD + k + l4;
                bhi[nt][0] = *(const uint32_t*)(ph);
                bhi[nt][1] = *(const uint32_t*)(ph + 8);
                blo[nt][0] = *(const uint32_t*)(pl);
                blo[nt][1] = *(const uint32_t*)(pl + 8);
            }
#pragma unroll
            for (int mt = 0; mt < 2; mt++)
#pragma unroll
                for (int nt = 0; nt < 4; nt++) {
                    mma_bf16(acc[mt][nt], ahi[mt], bhi[nt]);
                    mma_bf16(acc[mt][nt], ahi[mt], blo[nt]);
                    mma_bf16(acc[mt][nt], alo[mt], bhi[nt]);
                }
        }
    }

#pragma unroll
    for (int mt = 0; mt < 2; mt++) {
        int row0 = m0 + wm + mt * 16 + g4;
        int row1 = row0 + 8;
#pragma unroll
        for (int nt = 0; nt < 4; nt++) {
            int col = wn + nt * 8 + l4;
            float b0 = bias[col], b1 = bias[col + 1];
            float v0 = acc[mt][nt][0] + b0, v1 = acc[mt][nt][1] + b1;
            float v2 = acc[mt][nt][2] + b0, v3 = acc[mt][nt][3] + b1;
            if (relu) {
                v0 = fmaxf(v0, 0.f); v1 = fmaxf(v1, 0.f);
                v2 = fmaxf(v2, 0.f); v3 = fmaxf(v3, 0.f);
            }
            if (row0 < NN)
                __stcs((float2*)(out + (size_t)row0 * DD + col),
                       make_float2(v0, v1));
            if (row1 < NN)
                __stcs((float2*)(out + (size_t)row1 * DD + col),
                       make_float2(v2, v3));
        }
    }
}

// ===========================================================================
extern "C" void kernel_launch(void* const* d_in, const int* in_sizes, int n_in,
                              void* d_out, int out_size) {
    const float* h    = (const float*)d_in[0];
    const int*   esrc = (const int*)d_in[1];
    const int*   edst = (const int*)d_in[2];
    const float* fsw  = (const float*)d_in[3];
    const float* fdw  = (const float*)d_in[4];
    const float* al   = (const float*)d_in[5];
    const float* ar   = (const float*)d_in[6];
    const float* hb   = (const float*)d_in[7];
    float* out_final  = (float*)d_out;

    float *bufA, *bufB, *vl, *vr;
    __nv_bfloat16 *whi, *wlo;
    cudaGetSymbolAddress((void**)&bufA, g_bufA);
    cudaGetSymbolAddress((void**)&bufB, g_bufB);
    cudaGetSymbolAddress((void**)&vl,   g_vl);
    cudaGetSymbolAddress((void**)&vr,   g_vr);
    cudaGetSymbolAddress((void**)&whi,  g_whi);
    cudaGetSymbolAddress((void**)&wlo,  g_wlo);

    cudaFuncSetAttribute(gemm_agg_kernel,
                         cudaFuncAttributeMaxDynamicSharedMemorySize, SM_TOTAL);

    const int MT = (NN + MTILE - 1) / MTILE;   // 1563
    const int AB = (NR * NE + 255) / 256;      // 12500

    // 1: histogram (+ scan-state reset in tail blocks)
    hist_kernel<<<NR * FILLB + 7, 256>>>(edst);
    // 2: lookback scan + all-layer W prep + all-layer vecs
    scan_prep_kernel<<<SNB + 768 + 48, 512>>>(fsw, fdw, al, ar);
    // 3: CSR fill (+cdst) + layer-0 scores
    fill_scores_kernel<<<NR * FILLB + NN / 32, 256>>>(esrc, edst, h, vl, vr);

    const float* x = h;
    for (int l = 0; l < NL; l++) {
        float* out = (l == 0) ? bufB : (l == 1) ? bufA : out_final;

        if (l > 0)
            scores_kernel<<<NN / 32, 256>>>(x, vl + l * NR * DD,
                                            vr + l * NR * DD);
        alpha_kernel<<<AB, 256>>>();
        agg_kernel<<<dim3((NN + 7) / 8, NR), 256>>>(x);
        gemm_agg_kernel<<<MT, 256, SM_TOTAL>>>(out, hb + l * DD,
                                               l < NL - 1 ? 1 : 0,
                                               whi + (size_t)l * NR * DD * DD,
                                               wlo + (size_t)l * NR * DD * DD);
        x = out;
    }
}

// round 16
// speedup vs baseline: 1.8620x; 1.0080x over previous
#include <cuda_runtime.h>
#include <cuda_bf16.h>
#include <math.h>
#include <cstdint>

#define NN 100000
#define NR 8
#define NE 400000
#define DD 128
#define NL 3

#define SNB 1563                 // scan blocks: ceil(800000/512)
#define FILLB 1563               // fill blocks per relation: ceil(NE/256)

// ---------------- device scratch (static, no allocations) ----------------
__device__ float         g_bufA[NN * DD];
__device__ float         g_bufB[NN * DD];
__device__ float         g_el[NR * NN];
__device__ float         g_er[NR * NN];
__device__ float         g_vl[NL * NR * DD];
__device__ float         g_vr[NL * NR * DD];
__device__ __nv_bfloat16 g_whi[(size_t)NL * NR * DD * DD];
__device__ __nv_bfloat16 g_wlo[(size_t)NL * NR * DD * DD];
__device__ __nv_bfloat16 g_yhi[(size_t)NR * NN * DD];
__device__ __nv_bfloat16 g_ylo[(size_t)NR * NN * DD];
__device__ int           g_cnt[NR * NN];       // zero at start; reset by scan
__device__ int           g_fill[NR * NN];      // reset by scan
__device__ int           g_rowptrF[NR * NN + 1];
__device__ int           g_csrc[(size_t)NR * NE];
__device__ int           g_cdst[(size_t)NR * NE];
__device__ uint2         g_ws[(size_t)NR * NE];   // (w, src) per CSR slot
__device__ int           g_state[SNB];         // lookback: (value<<2)|flag
__device__ int           g_ticket;

// =================== kernel 1: hist + scan-state reset =====================
__global__ void hist_kernel(const int* __restrict__ edst) {
    int b = blockIdx.x;
    int tid = threadIdx.x;
    if (b < NR * FILLB) {
        int r = b / FILLB;
        int i = (b % FILLB) * 256 + tid;
        if (i < NE) {
            int d = edst[(size_t)r * NE + i];
            atomicAdd(&g_cnt[r * NN + d], 1);
        }
    } else {
        int i = (b - NR * FILLB) * 256 + tid;
        if (i < SNB) g_state[i] = 0;
        if (i == 0) g_ticket = 0;
    }
}

// =================== kernel 2: lookback scan + W prep + vecs ===============
__global__ void __launch_bounds__(512)
scan_prep_kernel(const float* __restrict__ fsw,
                 const float* __restrict__ fdw,
                 const float* __restrict__ al,
                 const float* __restrict__ ar) {
    int b = blockIdx.x;
    int tid = threadIdx.x;
    if (b < SNB) {
        __shared__ int sh[512];
        __shared__ int sbc[2];
        if (tid == 0) sbc[0] = atomicAdd(&g_ticket, 1);
        __syncthreads();
        int vid = sbc[0];
        int e = vid * 512 + tid;
        int v = 0;
        if (e < NR * NN) {
            v = g_cnt[e];
            g_cnt[e] = 0;
            g_fill[e] = 0;
        }
        sh[tid] = v;
        __syncthreads();
#pragma unroll
        for (int off = 1; off < 512; off <<= 1) {
            int t = (tid >= off) ? sh[tid - off] : 0;
            __syncthreads();
            sh[tid] += t;
            __syncthreads();
        }
        int incl = sh[tid];
        int btot = sh[511];
        if (tid == 0) {
            atomicExch(&g_state[vid], (btot << 2) | 1);
            int run = 0;
            int p = vid - 1;
            while (p >= 0) {
                int w = atomicAdd(&g_state[p], 0);
                int f = w & 3;
                if (f == 0) continue;
                run += (w >> 2);
                if (f == 2) break;
                p--;
            }
            atomicExch(&g_state[vid], ((run + btot) << 2) | 2);
            sbc[1] = run;
            if (vid == SNB - 1) {
                g_rowptrF[NR * NN] = run + btot;
                g_ticket = 0;
            }
        }
        __syncthreads();
        int run = sbc[1];
        if (e < NR * NN) g_rowptrF[e] = run + incl - v;
    } else if (b < SNB + 768) {
        int i = (b - SNB) * 512 + tid;
        float v = fsw[i];
        __nv_bfloat16 hi = __float2bfloat16_rn(v);
        g_whi[i] = hi;
        g_wlo[i] = __float2bfloat16_rn(v - __bfloat162float(hi));
    } else if (tid < 128) {
        int bb = b - SNB - 768;       // 0..47
        int l = bb >> 4;
        int sub = bb & 15;
        int r = sub >> 1;
        size_t wo = ((size_t)l * NR + r) * DD * DD;
        const float* W = (sub & 1) ? (fdw + wo) : (fsw + wo);
        const float* a = ((sub & 1) ? ar : al) + (l * NR + r) * DD;
        int k = tid;
        float s = 0.f;
#pragma unroll 8
        for (int j = 0; j < DD; j++) s += a[j] * W[j * DD + k];
        float* o = (sub & 1) ? g_vr : g_vl;
        o[(l * NR + r) * DD + k] = s;
    }
}

// -------- scores block body (256 threads) ----------------------------------
__device__ __forceinline__ void scores_block(const float* __restrict__ x,
                                             const float* __restrict__ vl,
                                             const float* __restrict__ vr,
                                             int n0) {
    __shared__ float xs[32][133];
    __shared__ float vv[16][DD];
    int tid = threadIdx.x;
    for (int i = tid; i < 16 * DD; i += 256) {
        int v = i >> 7, k = i & 127;
        vv[v][k] = (v < 8) ? vl[v * DD + k] : vr[(v - 8) * DD + k];
    }
    for (int i = tid; i < 32 * DD; i += 256) {
        int r = i >> 7, k = i & 127;
        xs[r][k] = x[(size_t)(n0 + r) * DD + k];
    }
    __syncthreads();

    int node = tid & 31;
    int v0 = (tid >> 5) * 2;
    float a0 = 0.f, a1 = 0.f;
#pragma unroll 8
    for (int k = 0; k < DD; k++) {
        float xv = xs[node][k];
        a0 += xv * vv[v0][k];
        a1 += xv * vv[v0 + 1][k];
    }
    int n = n0 + node;
    if (v0 < 8) g_el[v0 * NN + n] = a0;
    else        g_er[(v0 - 8) * NN + n] = a0;
    int v1 = v0 + 1;
    if (v1 < 8) g_el[v1 * NN + n] = a1;
    else        g_er[(v1 - 8) * NN + n] = a1;
}

// =================== kernel 3: CSR fill (+cdst) + layer-0 scores ===========
__global__ void __launch_bounds__(256)
fill_scores_kernel(const int* __restrict__ esrc,
                   const int* __restrict__ edst,
                   const float* __restrict__ x,
                   const float* __restrict__ vl0,
                   const float* __restrict__ vr0) {
    int b = blockIdx.x;
    if (b < NR * FILLB) {
        int r = b / FILLB;
        int i = (b % FILLB) * 256 + threadIdx.x;
        if (i < NE) {
            int d = edst[(size_t)r * NE + i];
            int s = esrc[(size_t)r * NE + i];
            int pos = g_rowptrF[r * NN + d] + atomicAdd(&g_fill[r * NN + d], 1);
            g_csrc[pos] = s;
            g_cdst[pos] = d;
        }
    } else {
        scores_block(x, vl0, vr0, (b - NR * FILLB) * 32);
    }
}

// =================== standalone scores (layers 1,2) ========================
__global__ void __launch_bounds__(256)
scores_kernel(const float* __restrict__ x,
              const float* __restrict__ vl,
              const float* __restrict__ vr) {
    scores_block(x, vl, vr, blockIdx.x * 32);
}

// =================== alpha: w = exp(leaky(el[s]+er[d])) per CSR slot =======
__global__ void __launch_bounds__(256)
alpha_kernel() {
    int i = blockIdx.x * 256 + threadIdx.x;
    if (i >= NR * NE) return;
    int r = i / NE;
    int s = g_csrc[i];
    int d = g_cdst[i];
    float v = g_el[(size_t)r * NN + s] + g_er[(size_t)r * NN + d];
    v = v > 0.f ? v : 0.2f * v;
    float w = expf(v);
    g_ws[i] = make_uint2(__float_as_uint(w), (unsigned)s);
}

// =================== aggregation: 4-edge unrolled inner loop (MLP=4) =======
__device__ __forceinline__ uint32_t pack_bf2(__nv_bfloat16 a, __nv_bfloat16 b) {
    return (uint32_t)__bfloat16_as_ushort(a) |
           ((uint32_t)__bfloat16_as_ushort(b) << 16);
}

__global__ void __launch_bounds__(256)
agg_kernel(const float* __restrict__ x) {
    int lane = threadIdx.x & 31;
    int d = blockIdx.x * 8 + (threadIdx.x >> 5);
    int r = blockIdx.y;
    if (d >= NN) return;

    const int* rp = g_rowptrF + (size_t)r * NN;
    const uint2* ws = g_ws;
    const float4* x4 = (const float4*)x;

    int st = rp[d], en = rp[d + 1];
    float ax = 0.f, ay = 0.f, az = 0.f, aw = 0.f;
    float den = 0.f;
    int e = st;
    for (; e + 4 <= en; e += 4) {
        uint2 p0 = ws[e];
        uint2 p1 = ws[e + 1];
        uint2 p2 = ws[e + 2];
        uint2 p3 = ws[e + 3];
        float w0 = __uint_as_float(p0.x);
        float w1 = __uint_as_float(p1.x);
        float w2 = __uint_as_float(p2.x);
        float w3 = __uint_as_float(p3.x);
        float4 v0 = x4[(size_t)(int)p0.y * 32 + lane];
        float4 v1 = x4[(size_t)(int)p1.y * 32 + lane];
        float4 v2 = x4[(size_t)(int)p2.y * 32 + lane];
        float4 v3 = x4[(size_t)(int)p3.y * 32 + lane];
        den += (w0 + w1) + (w2 + w3);
        ax += w0 * v0.x; ay += w0 * v0.y; az += w0 * v0.z; aw += w0 * v0.w;
        ax += w1 * v1.x; ay += w1 * v1.y; az += w1 * v1.z; aw += w1 * v1.w;
        ax += w2 * v2.x; ay += w2 * v2.y; az += w2 * v2.z; aw += w2 * v2.w;
        ax += w3 * v3.x; ay += w3 * v3.y; az += w3 * v3.z; aw += w3 * v3.w;
    }
    if (e + 2 <= en) {
        uint2 p0 = ws[e];
        uint2 p1 = ws[e + 1];
        float w0 = __uint_as_float(p0.x);
        float w1 = __uint_as_float(p1.x);
        float4 v0 = x4[(size_t)(int)p0.y * 32 + lane];
        float4 v1 = x4[(size_t)(int)p1.y * 32 + lane];
        den += w0 + w1;
        ax += w0 * v0.x; ay += w0 * v0.y; az += w0 * v0.z; aw += w0 * v0.w;
        ax += w1 * v1.x; ay += w1 * v1.y; az += w1 * v1.z; aw += w1 * v1.w;
        e += 2;
    }
    if (e < en) {
        uint2 p = ws[e];
        float w = __uint_as_float(p.x);
        float4 xv = x4[(size_t)(int)p.y * 32 + lane];
        den += w;
        ax += w * xv.x; ay += w * xv.y; az += w * xv.z; aw += w * xv.w;
    }
    float inv = den > 0.f ? 1.f / den : 0.f;
    ax *= inv; ay *= inv; az *= inv; aw *= inv;

    __nv_bfloat16 h0 = __float2bfloat16_rn(ax);
    __nv_bfloat16 h1 = __float2bfloat16_rn(ay);
    __nv_bfloat16 h2 = __float2bfloat16_rn(az);
    __nv_bfloat16 h3 = __float2bfloat16_rn(aw);
    __nv_bfloat16 l0 = __float2bfloat16_rn(ax - __bfloat162float(h0));
    __nv_bfloat16 l1 = __float2bfloat16_rn(ay - __bfloat162float(h1));
    __nv_bfloat16 l2 = __float2bfloat16_rn(az - __bfloat162float(h2));
    __nv_bfloat16 l3 = __float2bfloat16_rn(aw - __bfloat162float(h3));
    size_t off = ((size_t)r * NN + d) * DD + lane * 4;
    __stcs((uint2*)(g_yhi + off), make_uint2(pack_bf2(h0, h1), pack_bf2(h2, h3)));
    __stcs((uint2*)(g_ylo + off), make_uint2(pack_bf2(l0, l1), pack_bf2(l2, l3)));
}

// =================== HMMA GEMM (R11-proven, MTILE=64) ======================
#define PAD 136
#define MTILE 64

#define SA_HI 0
#define SA_LO (MTILE * PAD * 2)
#define SB_HI (2 * MTILE * PAD * 2)
#define SB_LO (SB_HI + 128 * PAD * 2)
#define SM_TOTAL (SB_LO + 128 * PAD * 2)   // 104448

__device__ __forceinline__ void mma_bf16(float* c, const uint32_t* a,
                                         const uint32_t* b) {
    asm volatile(
        "mma.sync.aligned.m16n8k16.row.col.f32.bf16.bf16.f32 "
        "{%0,%1,%2,%3}, {%4,%5,%6,%7}, {%8,%9}, {%0,%1,%2,%3};"
        : "+f"(c[0]), "+f"(c[1]), "+f"(c[2]), "+f"(c[3])
        : "r"(a[0]), "r"(a[1]), "r"(a[2]), "r"(a[3]), "r"(b[0]), "r"(b[1]));
}

__global__ void __launch_bounds__(256, 2)
gemm_agg_kernel(float* __restrict__ out, const float* __restrict__ bias,
                int relu,
                const __nv_bfloat16* __restrict__ whiL,
                const __nv_bfloat16* __restrict__ wloL) {
    extern __shared__ char smem[];
    __nv_bfloat16* Ahi = (__nv_bfloat16*)(smem + SA_HI);
    __nv_bfloat16* Alo = (__nv_bfloat16*)(smem + SA_LO);
    __nv_bfloat16* Bhi = (__nv_bfloat16*)(smem + SB_HI);
    __nv_bfloat16* Blo = (__nv_bfloat16*)(smem + SB_LO);

    int tid = threadIdx.x;
    int wid = tid >> 5;
    int lane = tid & 31;
    int m0 = blockIdx.x * MTILE;

    int wm = (wid >> 2) * 32;
    int wn = (wid & 3) * 32;
    int g4 = lane >> 2;
    int l4 = (lane & 3) * 2;

    float acc[2][4][4];
#pragma unroll
    for (int mt = 0; mt < 2; mt++)
#pragma unroll
        for (int nt = 0; nt < 4; nt++)
#pragma unroll
            for (int j = 0; j < 4; j++) acc[mt][nt][j] = 0.f;

    for (int r = 0; r < NR; r++) {
        __syncthreads();

        const uint4* whi4 = (const uint4*)(whiL + (size_t)r * DD * DD);
        const uint4* wlo4 = (const uint4*)(wloL + (size_t)r * DD * DD);
        const uint4* yhi4 = (const uint4*)g_yhi;
        const uint4* ylo4 = (const uint4*)g_ylo;
#pragma unroll
        for (int it = 0; it < 8; it++) {
            int idx = tid + it * 256;
            int row = idx >> 4, c8 = idx & 15;
            *(uint4*)(Bhi + row * PAD + c8 * 8) = whi4[idx];
            *(uint4*)(Blo + row * PAD + c8 * 8) = wlo4[idx];
        }
#pragma unroll
        for (int it = 0; it < 4; it++) {
            int idx = tid + it * 256;
            int row = idx >> 4, c8 = idx & 15;
            uint4 vhi = make_uint4(0, 0, 0, 0), vlo = make_uint4(0, 0, 0, 0);
            if (m0 + row < NN) {
                size_t gi = ((size_t)r * NN + m0 + row) * 16 + c8;
                vhi = __ldcs(&yhi4[gi]);
                vlo = __ldcs(&ylo4[gi]);
            }
            *(uint4*)(Ahi + row * PAD + c8 * 8) = vhi;
            *(uint4*)(Alo + row * PAD + c8 * 8) = vlo;
        }
        __syncthreads();

#pragma unroll
        for (int kk = 0; kk < 8; kk++) {
            int k = kk * 16;
            uint32_t ahi[2][4], alo[2][4];
#pragma unroll
            for (int mt = 0; mt < 2; mt++) {
                int r0 = wm + mt * 16 + g4;
                const __nv_bfloat16* ph = Ahi + r0 * PAD + k + l4;
                const __nv_bfloat16* pl = Alo + r0 * PAD + k + l4;
                ahi[mt][0] = *(const uint32_t*)(ph);
                ahi[mt][1] = *(const uint32_t*)(ph + 8 * PAD);
                ahi[mt][2] = *(const uint32_t*)(ph + 8);
                ahi[mt][3] = *(const uint32_t*)(ph + 8 * PAD + 8);
                alo[mt][0] = *(const uint32_t*)(pl);
                alo[mt][1] = *(const uint32_t*)(pl + 8 * PAD);
                alo[mt][2] = *(const uint32_t*)(pl + 8);
                alo[mt][3] = *(const uint32_t*)(pl + 8 * PAD + 8);
            }
            uint32_t bhi[4][2], blo[4][2];
#pragma unroll
            for (int nt = 0; nt < 4; nt++) {
                int n = wn + nt * 8 + g4;
                const __nv_bfloat16* ph = Bhi + n * PAD + k + l4;
                const __nv_bfloat16* pl = Blo + n * PAD + k + l4;
                bhi[nt][0] = *(const uint32_t*)(ph);
                bhi[nt][1] = *(const uint32_t*)(ph + 8);
                blo[nt][0] = *(const uint32_t*)(pl);
                blo[nt][1] = *(const uint32_t*)(pl + 8);
            }
#pragma unroll
            for (int mt = 0; mt < 2; mt++)
#pragma unroll
                for (int nt = 0; nt < 4; nt++) {
                    mma_bf16(acc[mt][nt], ahi[mt], bhi[nt]);
                    mma_bf16(acc[mt][nt], ahi[mt], blo[nt]);
                    mma_bf16(acc[mt][nt], alo[mt], bhi[nt]);
                }
        }
    }

#pragma unroll
    for (int mt = 0; mt < 2; mt++) {
        int row0 = m0 + wm + mt * 16 + g4;
        int row1 = row0 + 8;
#pragma unroll
        for (int nt = 0; nt < 4; nt++) {
            int col = wn + nt * 8 + l4;
            float b0 = bias[col], b1 = bias[col + 1];
            float v0 = acc[mt][nt][0] + b0, v1 = acc[mt][nt][1] + b1;
            float v2 = acc[mt][nt][2] + b0, v3 = acc[mt][nt][3] + b1;
            if (relu) {
                v0 = fmaxf(v0, 0.f); v1 = fmaxf(v1, 0.f);
                v2 = fmaxf(v2, 0.f); v3 = fmaxf(v3, 0.f);
            }
            if (row0 < NN)
                __stcs((float2*)(out + (size_t)row0 * DD + col),
                       make_float2(v0, v1));
            if (row1 < NN)
                __stcs((float2*)(out + (size_t)row1 * DD + col),
                       make_float2(v2, v3));
        }
    }
}

// ===========================================================================
extern "C" void kernel_launch(void* const* d_in, const int* in_sizes, int n_in,
                              void* d_out, int out_size) {
    const float* h    = (const float*)d_in[0];
    const int*   esrc = (const int*)d_in[1];
    const int*   edst = (const int*)d_in[2];
    const float* fsw  = (const float*)d_in[3];
    const float* fdw  = (const float*)d_in[4];
    const float* al   = (const float*)d_in[5];
    const float* ar   = (const float*)d_in[6];
    const float* hb   = (const float*)d_in[7];
    float* out_final  = (float*)d_out;

    float *bufA, *bufB, *vl, *vr;
    __nv_bfloat16 *whi, *wlo;
    cudaGetSymbolAddress((void**)&bufA, g_bufA);
    cudaGetSymbolAddress((void**)&bufB, g_bufB);
    cudaGetSymbolAddress((void**)&vl,   g_vl);
    cudaGetSymbolAddress((void**)&vr,   g_vr);
    cudaGetSymbolAddress((void**)&whi,  g_whi);
    cudaGetSymbolAddress((void**)&wlo,  g_wlo);

    cudaFuncSetAttribute(gemm_agg_kernel,
                         cudaFuncAttributeMaxDynamicSharedMemorySize, SM_TOTAL);

    const int MT = (NN + MTILE - 1) / MTILE;   // 1563
    const int AB = (NR * NE + 255) / 256;      // 12500

    // 1: histogram (+ scan-state reset in tail blocks)
    hist_kernel<<<NR * FILLB + 7, 256>>>(edst);
    // 2: lookback scan + all-layer W prep + all-layer vecs
    scan_prep_kernel<<<SNB + 768 + 48, 512>>>(fsw, fdw, al, ar);
    // 3: CSR fill (+cdst) + layer-0 scores
    fill_scores_kernel<<<NR * FILLB + NN / 32, 256>>>(esrc, edst, h, vl, vr);

    const float* x = h;
    for (int l = 0; l < NL; l++) {
        float* out = (l == 0) ? bufB : (l == 1) ? bufA : out_final;

        if (l > 0)
            scores_kernel<<<NN / 32, 256>>>(x, vl + l * NR * DD,
                                            vr + l * NR * DD);
        alpha_kernel<<<AB, 256>>>();
        agg_kernel<<<dim3((NN + 7) / 8, NR), 256>>>(x);
        gemm_agg_kernel<<<MT, 256, SM_TOTAL>>>(out, hb + l * DD,
                                               l < NL - 1 ? 1 : 0,
                                               whi + (size_t)l * NR * DD * DD,
                                               wlo + (size_t)l * NR * DD * DD);
        x = out;
    }
}